// round 11
// baseline (speedup 1.0000x reference)
#include <cuda_runtime.h>
#include <cstdint>

static const int NN = 50000;
static const int NE = 800000;
static const int FD = 128;
static const int HD = 256;
static const int NG = 128;
static const int NC = 10;
static const int NL = 3;

// Scratch
__device__ float    g_h[(long long)NN * HD];
__device__ float    g_z[(long long)NN * HD];
__device__ float    g_inv[NN];
__device__ int      g_deg[NN];
__device__ int      g_rowptr[NN + 1];
__device__ int      g_pos[NN];
__device__ int      g_csrc[NE];
__device__ int      g_bsum[256];
__device__ int      g_boff[256];
__device__ float    g_R[NL * NG * HD];
__device__ unsigned g_Bsplit[(FD * HD + NL * HD * HD) * 2];
__device__ float    g_gmsum[NG * HD];
__device__ int      g_cnt[NG];
__device__ float    g_gm[NG * HD];

// ---------------- init ----------------
__global__ void k_init() {
    int i = blockIdx.x * blockDim.x + threadIdx.x;
    if (i < NN) g_deg[i] = 0;
    if (i < NG * HD) g_gmsum[i] = 0.f;
    if (i < NG) g_cnt[i] = 0;
}
__global__ void k_count(const int* __restrict__ dst, const int* __restrict__ batch) {
    int e = blockIdx.x * blockDim.x + threadIdx.x;
    if (e < NE) atomicAdd(&g_deg[dst[e]], 1);
    if (e < NN) atomicAdd(&g_cnt[batch[e]], 1);
}

// ---------------- TF32 helpers ----------------
__device__ __forceinline__ unsigned f2tf(float f) {
    unsigned u;
    asm("cvt.rna.tf32.f32 %0, %1;" : "=r"(u) : "f"(f));
    return u;
}
__device__ __forceinline__ void split_tf32(float f, unsigned& hi, unsigned& lo) {
    hi = f2tf(f);
    lo = f2tf(f - __uint_as_float(hi));
}
__device__ __forceinline__ void mma_tf32(float4& c, const unsigned a[4], const unsigned b[2]) {
    asm volatile(
        "mma.sync.aligned.m16n8k8.row.col.f32.tf32.tf32.f32 "
        "{%0,%1,%2,%3}, {%4,%5,%6,%7}, {%8,%9}, {%0,%1,%2,%3};"
        : "+f"(c.x), "+f"(c.y), "+f"(c.z), "+f"(c.w)
        : "r"(a[0]), "r"(a[1]), "r"(a[2]), "r"(a[3]), "r"(b[0]), "r"(b[1]));
}

// ---------------- weight pre-split ----------------
__global__ void k_bsplit(const float* __restrict__ W0, const float* __restrict__ Ws) {
    int i = blockIdx.x * blockDim.x + threadIdx.x;
    const int total = FD * HD + NL * HD * HD;
    if (i >= total) return;
    float v = (i < FD * HD) ? W0[i] : Ws[i - FD * HD];
    unsigned hi, lo;
    split_tf32(v, hi, lo);
    g_Bsplit[2 * i]     = hi;
    g_Bsplit[2 * i + 1] = lo;
}

// ---------------- CSR build ----------------
#define SCAN_B 256
__global__ void k_scan1() {
    __shared__ int sh[SCAN_B];
    int i = blockIdx.x * SCAN_B + threadIdx.x;
    int v = (i < NN) ? g_deg[i] : 0;
    sh[threadIdx.x] = v;
    __syncthreads();
    for (int s = SCAN_B / 2; s > 0; s >>= 1) {
        if (threadIdx.x < s) sh[threadIdx.x] += sh[threadIdx.x + s];
        __syncthreads();
    }
    if (threadIdx.x == 0) g_bsum[blockIdx.x] = sh[0];
}
__global__ void k_scan2p(int nblocks) {
    __shared__ int sh[256];
    int t = threadIdx.x;
    int v = (t < nblocks) ? g_bsum[t] : 0;
    sh[t] = v;
    __syncthreads();
    for (int s = 1; s < 256; s <<= 1) {
        int u = (t >= s) ? sh[t - s] : 0;
        __syncthreads();
        sh[t] += u;
        __syncthreads();
    }
    if (t < nblocks) g_boff[t] = sh[t] - v;
    if (t == 255) g_rowptr[NN] = sh[255];
}
__global__ void k_scan3() {
    __shared__ int sh[SCAN_B];
    int i = blockIdx.x * SCAN_B + threadIdx.x;
    int v = (i < NN) ? g_deg[i] : 0;
    sh[threadIdx.x] = v;
    __syncthreads();
    for (int s = 1; s < SCAN_B; s <<= 1) {
        int t = (threadIdx.x >= s) ? sh[threadIdx.x - s] : 0;
        __syncthreads();
        sh[threadIdx.x] += t;
        __syncthreads();
    }
    if (i < NN) {
        int excl = g_boff[blockIdx.x] + sh[threadIdx.x] - v;
        g_rowptr[i] = excl;
        g_pos[i] = excl;
        g_inv[i] = rsqrtf((float)(v + 1));
    }
}
__global__ void k_scatter(const int* __restrict__ src, const int* __restrict__ dst) {
    int e = blockIdx.x * blockDim.x + threadIdx.x;
    if (e >= NE) return;
    int d = dst[e];
    int slot = atomicAdd(&g_pos[d], 1);
    g_csrc[slot] = src[e];
}

// ---------------- small GEMM: g_R[l] = gh @ Ws[l] ----------------
__global__ __launch_bounds__(256)
void k_rgemm(const float* __restrict__ gh, const float* __restrict__ Ws) {
    __shared__ float Ag[128 * 36];
    __shared__ float Bg[32 * 132];
    const float* B = Ws + (size_t)blockIdx.y * HD * HD;
    const int colBase = blockIdx.x * 128;
    const int tid = threadIdx.x;
    const int tx = tid & 15, ty = tid >> 4;
    float acc[8][8];
#pragma unroll
    for (int i = 0; i < 8; i++)
#pragma unroll
        for (int j = 0; j < 8; j++) acc[i][j] = 0.f;

    const int ar = tid >> 1, ak = (tid & 1) * 16;
    const int br = tid >> 3, bc = (tid & 7) * 16;
    for (int kt = 0; kt < HD; kt += 32) {
#pragma unroll
        for (int q = 0; q < 4; q++) {
            float4 v = *(const float4*)(gh + (size_t)ar * HD + kt + ak + 4 * q);
            *(float4*)&Ag[ar * 36 + ak + 4 * q] = v;
            float4 w = *(const float4*)(B + (size_t)(kt + br) * HD + colBase + bc + 4 * q);
            *(float4*)&Bg[br * 132 + bc + 4 * q] = w;
        }
        __syncthreads();
#pragma unroll
        for (int kk = 0; kk < 32; kk++) {
            float a[8], b[8];
#pragma unroll
            for (int i = 0; i < 8; i++) a[i] = Ag[(ty * 8 + i) * 36 + kk];
            *(float4*)(b)     = *(const float4*)&Bg[kk * 132 + tx * 8];
            *(float4*)(b + 4) = *(const float4*)&Bg[kk * 132 + tx * 8 + 4];
#pragma unroll
            for (int i = 0; i < 8; i++)
#pragma unroll
                for (int j = 0; j < 8; j++) acc[i][j] = fmaf(a[i], b[j], acc[i][j]);
        }
        __syncthreads();
    }
    float* outp = g_R + (size_t)blockIdx.y * NG * HD;
#pragma unroll
    for (int i = 0; i < 8; i++)
#pragma unroll
        for (int j = 0; j < 2; j++)
            *(float4*)(outp + (size_t)(ty * 8 + i) * HD + colBase + tx * 8 + 4 * j) =
                make_float4(acc[i][4 * j], acc[i][4 * j + 1], acc[i][4 * j + 2], acc[i][4 * j + 3]);
}

// ---------------- main tensor GEMM (pre-split A staged + pre-split B) ----------------
// Inner loop: pure LDS.64 + MMA, zero conversion ALU.
// LIDX < 0: A = g_z (N x KD), out = g_h, epilogue += bias[col], B = W0 split
// LIDX >= 0: A = g_h (N x 256), out = g_z, epilogue += g_R[LIDX][batch[row]], B = Ws[LIDX] split
#define AS2_W 40    // u32 stride per A row: 16k*2 + 8 pad; (40/2) % 16 == 4 -> conflict-free frags
#define BS2_W 264
template<int KD, int LIDX>
__global__ __launch_bounds__(256, 2)
void k_gemm(const int* __restrict__ batch, const float* __restrict__ bias) {
    __shared__ unsigned As[128 * AS2_W];   // 20.5 KB
    __shared__ unsigned Bs[16 * BS2_W];    // 16.9 KB
    const int tid  = threadIdx.x;
    const int lane = tid & 31;
    const int warp = tid >> 5;
    const int wm = warp >> 1;
    const int wn = warp & 1;
    const int rowBase = blockIdx.x * 128;
    const int colBase = blockIdx.y * 128;

    const int arow = tid >> 1;          // 0..127
    const int akb  = (tid & 1) * 8;     // 0 or 8 (k offset within 16)
    const int bk   = tid >> 4;          // 0..15
    const int bq   = (tid & 15) * 4;    // u32 offset within B row

    const int aRowG = rowBase + arow;
    const bool rowOK = (aRowG < NN);
    const float* aPtr = (LIDX < 0 ? (const float*)g_z : (const float*)g_h) + (size_t)aRowG * KD;
    float* outBase = (LIDX < 0 ? g_h : g_z);
    const unsigned* B2 = g_Bsplit + (LIDX < 0 ? 0 : ((size_t)FD * HD + (size_t)LIDX * HD * HD) * 2);

    float4 acc[2][8];
#pragma unroll
    for (int i = 0; i < 2; i++)
#pragma unroll
        for (int j = 0; j < 8; j++) acc[i][j] = make_float4(0.f, 0.f, 0.f, 0.f);

    for (int kt = 0; kt < KD; kt += 16) {
        // ---- stage A: load 8 floats, split once, store (hi,lo) pairs ----
        {
            float4 a0 = make_float4(0.f, 0.f, 0.f, 0.f);
            float4 a1 = a0;
            if (rowOK) {
                a0 = *(const float4*)(aPtr + kt + akb);
                a1 = *(const float4*)(aPtr + kt + akb + 4);
            }
            float av[8] = {a0.x, a0.y, a0.z, a0.w, a1.x, a1.y, a1.z, a1.w};
#pragma unroll
            for (int p = 0; p < 4; p++) {
                unsigned h0, l0, h1, l1;
                split_tf32(av[2 * p],     h0, l0);
                split_tf32(av[2 * p + 1], h1, l1);
                *(uint4*)&As[arow * AS2_W + (akb + 2 * p) * 2] = make_uint4(h0, l0, h1, l1);
            }
        }
        // ---- stage pre-split B (16 k rows) ----
        {
            const unsigned* bg = B2 + ((size_t)(kt + bk) * HD + colBase) * 2 + bq;
#pragma unroll
            for (int i = 0; i < 4; i++) {
                uint4 v = *(const uint4*)(bg + i * 64);
                *(uint4*)&Bs[bk * BS2_W + bq + i * 64] = v;
            }
        }
        __syncthreads();

#pragma unroll
        for (int k8 = 0; k8 < 2; k8++) {
            const int kk = k8 * 8 + (lane & 3);
            unsigned ah[2][4], al[2][4];
#pragma unroll
            for (int i = 0; i < 2; i++) {
                int r = wm * 32 + i * 16 + (lane >> 2);
                uint2 p;
                p = *(const uint2*)&As[r * AS2_W + kk * 2];             ah[i][0] = p.x; al[i][0] = p.y;
                p = *(const uint2*)&As[(r + 8) * AS2_W + kk * 2];       ah[i][1] = p.x; al[i][1] = p.y;
                p = *(const uint2*)&As[r * AS2_W + (kk + 4) * 2];       ah[i][2] = p.x; al[i][2] = p.y;
                p = *(const uint2*)&As[(r + 8) * AS2_W + (kk + 4) * 2]; ah[i][3] = p.x; al[i][3] = p.y;
            }
#pragma unroll
            for (int h = 0; h < 2; h++) {
                unsigned bh[4][2], bl[4][2];
#pragma unroll
                for (int j = 0; j < 4; j++) {
                    int c = wn * 64 + h * 32 + j * 8 + (lane >> 2);
                    uint2 p0 = *(const uint2*)&Bs[kk * BS2_W + c * 2];
                    uint2 p1 = *(const uint2*)&Bs[(kk + 4) * BS2_W + c * 2];
                    bh[j][0] = p0.x; bl[j][0] = p0.y;
                    bh[j][1] = p1.x; bl[j][1] = p1.y;
                }
#pragma unroll
                for (int i = 0; i < 2; i++)
#pragma unroll
                    for (int j = 0; j < 4; j++) {
                        float4& c4 = acc[i][h * 4 + j];
                        mma_tf32(c4, ah[i], bh[j]);
                        mma_tf32(c4, ah[i], bl[j]);
                        mma_tf32(c4, al[i], bh[j]);
                    }
            }
        }
        __syncthreads();
    }

    // ---- epilogue ----
#pragma unroll
    for (int i = 0; i < 2; i++) {
        int r0 = rowBase + wm * 32 + i * 16 + (lane >> 2);
        const float* Ra = nullptr;
        const float* Rb = nullptr;
        if (LIDX >= 0) {
            if (r0 < NN)     Ra = g_R + (size_t)LIDX * NG * HD + (size_t)batch[r0] * HD;
            if (r0 + 8 < NN) Rb = g_R + (size_t)LIDX * NG * HD + (size_t)batch[r0 + 8] * HD;
        }
#pragma unroll
        for (int j = 0; j < 8; j++) {
            int c = colBase + wn * 64 + j * 8 + 2 * (lane & 3);
            float4 v = acc[i][j];
            float2 bc2 = make_float2(0.f, 0.f);
            if (LIDX < 0) bc2 = *(const float2*)(bias + c);
            if (r0 < NN) {
                float2 o = make_float2(v.x, v.y);
                if (LIDX >= 0) { float2 r = *(const float2*)(Ra + c); o.x += r.x; o.y += r.y; }
                else           { o.x += bc2.x; o.y += bc2.y; }
                *(float2*)(outBase + (size_t)r0 * HD + c) = o;
            }
            if (r0 + 8 < NN) {
                float2 o = make_float2(v.z, v.w);
                if (LIDX >= 0) { float2 r = *(const float2*)(Rb + c); o.x += r.x; o.y += r.y; }
                else           { o.x += bc2.x; o.y += bc2.y; }
                *(float2*)(outBase + (size_t)(r0 + 8) * HD + c) = o;
            }
        }
    }
}

// ---------------- propagation ----------------
__device__ __forceinline__ void acc4(float4& acc, const float4& u, float wt) {
    acc.x = fmaf(u.x, wt, acc.x);
    acc.y = fmaf(u.y, wt, acc.y);
    acc.z = fmaf(u.z, wt, acc.z);
    acc.w = fmaf(u.w, wt, acc.w);
}

// z = P x  (N x 128). One warp per node.
__global__ __launch_bounds__(256)
void k_prop_x(const float* __restrict__ x) {
    int node = blockIdx.x * 8 + (threadIdx.x >> 5);
    int lane = threadIdx.x & 31;
    if (node >= NN) return;
    int off = lane * 4;
    float invd = g_inv[node];
    float sq = invd * invd;
    float4 h0 = *(const float4*)(x + (size_t)node * FD + off);
    float4 acc = make_float4(h0.x * sq, h0.y * sq, h0.z * sq, h0.w * sq);
    int e   = g_rowptr[node];
    int end = g_rowptr[node + 1];
    for (; e + 8 <= end; e += 8) {
        int s[8];
        float wt[8];
        float4 u[8];
#pragma unroll
        for (int q = 0; q < 8; q++) s[q] = g_csrc[e + q];
#pragma unroll
        for (int q = 0; q < 8; q++) u[q] = *(const float4*)(x + (size_t)s[q] * FD + off);
#pragma unroll
        for (int q = 0; q < 8; q++) wt[q] = g_inv[s[q]] * invd;
#pragma unroll
        for (int q = 0; q < 8; q++) acc4(acc, u[q], wt[q]);
    }
    for (; e < end; e++) {
        int s0 = g_csrc[e];
        float w0 = g_inv[s0] * invd;
        float4 u0 = *(const float4*)(x + (size_t)s0 * FD + off);
        acc4(acc, u0, w0);
    }
    *(float4*)(g_z + (size_t)node * FD + off) = acc;
}

// h = relu(P t + bias), t in g_z (N x 256), out g_h. 2 warps per node.
__global__ __launch_bounds__(256)
void k_prop(const float* __restrict__ bias) {
    int node = blockIdx.x * 4 + (threadIdx.x >> 6);
    int half = (threadIdx.x >> 5) & 1;
    int lane = threadIdx.x & 31;
    if (node >= NN) return;
    int off = half * 128 + lane * 4;
    float invd = g_inv[node];
    float sq = invd * invd;
    float4 h0 = *(const float4*)(g_z + (size_t)node * HD + off);
    float4 b0 = *(const float4*)(bias + off);
    float4 acc = make_float4(fmaf(h0.x, sq, b0.x), fmaf(h0.y, sq, b0.y),
                             fmaf(h0.z, sq, b0.z), fmaf(h0.w, sq, b0.w));
    int e   = g_rowptr[node];
    int end = g_rowptr[node + 1];
    for (; e + 8 <= end; e += 8) {
        int s[8];
        float wt[8];
        float4 u[8];
#pragma unroll
        for (int q = 0; q < 8; q++) s[q] = g_csrc[e + q];
#pragma unroll
        for (int q = 0; q < 8; q++) u[q] = *(const float4*)(g_z + (size_t)s[q] * HD + off);
#pragma unroll
        for (int q = 0; q < 8; q++) wt[q] = g_inv[s[q]] * invd;
#pragma unroll
        for (int q = 0; q < 8; q++) acc4(acc, u[q], wt[q]);
    }
    for (; e + 2 <= end; e += 2) {
        int s0 = g_csrc[e], s1 = g_csrc[e + 1];
        float4 u0 = *(const float4*)(g_z + (size_t)s0 * HD + off);
        float4 u1 = *(const float4*)(g_z + (size_t)s1 * HD + off);
        float w0 = g_inv[s0] * invd, w1 = g_inv[s1] * invd;
        acc4(acc, u0, w0);
        acc4(acc, u1, w1);
    }
    if (e < end) {
        int s0 = g_csrc[e];
        float w0 = g_inv[s0] * invd;
        float4 u0 = *(const float4*)(g_z + (size_t)s0 * HD + off);
        acc4(acc, u0, w0);
    }
    acc.x = fmaxf(acc.x, 0.f); acc.y = fmaxf(acc.y, 0.f);
    acc.z = fmaxf(acc.z, 0.f); acc.w = fmaxf(acc.w, 0.f);
    *(float4*)(g_h + (size_t)node * HD + off) = acc;
}

// ---------------- pooling (reads g_h) ----------------
#define POOL_NPW 8
__global__ void k_pool_accum(const int* __restrict__ batch) {
    int w = (blockIdx.x * blockDim.x + threadIdx.x) >> 5;
    int lane = threadIdx.x & 31;
    int n0 = w * POOL_NPW;
    if (n0 >= NN) return;
    int nend = n0 + POOL_NPW;
    if (nend > NN) nend = NN;
    float4 a0 = make_float4(0.f, 0.f, 0.f, 0.f);
    float4 a1 = a0;
    int cur = batch[n0];
    for (int n = n0; n < nend; n++) {
        int b = batch[n];
        if (b != cur) {
            float* gs = g_gmsum + (size_t)cur * HD;
            asm volatile("red.global.add.v4.f32 [%0], {%1,%2,%3,%4};"
                         :: "l"(gs + lane * 4), "f"(a0.x), "f"(a0.y), "f"(a0.z), "f"(a0.w) : "memory");
            asm volatile("red.global.add.v4.f32 [%0], {%1,%2,%3,%4};"
                         :: "l"(gs + 128 + lane * 4), "f"(a1.x), "f"(a1.y), "f"(a1.z), "f"(a1.w) : "memory");
            a0 = make_float4(0.f, 0.f, 0.f, 0.f);
            a1 = a0;
            cur = b;
        }
        float4 v0 = *(const float4*)(g_h + (size_t)n * HD + lane * 4);
        float4 v1 = *(const float4*)(g_h + (size_t)n * HD + 128 + lane * 4);
        a0.x += v0.x; a0.y += v0.y; a0.z += v0.z; a0.w += v0.w;
        a1.x += v1.x; a1.y += v1.y; a1.z += v1.z; a1.w += v1.w;
    }
    float* gs = g_gmsum + (size_t)cur * HD;
    asm volatile("red.global.add.v4.f32 [%0], {%1,%2,%3,%4};"
                 :: "l"(gs + lane * 4), "f"(a0.x), "f"(a0.y), "f"(a0.z), "f"(a0.w) : "memory");
    asm volatile("red.global.add.v4.f32 [%0], {%1,%2,%3,%4};"
                 :: "l"(gs + 128 + lane * 4), "f"(a1.x), "f"(a1.y), "f"(a1.z), "f"(a1.w) : "memory");
}
__global__ void k_pool_final(const float* __restrict__ gh, float* __restrict__ out) {
    int t = blockIdx.x * blockDim.x + threadIdx.x;
    if (t >= NG * HD) return;
    int g = t / HD;
    float cnt = (float)max(g_cnt[g], 1);
    float v = g_gmsum[t] / cnt + gh[t];
    g_gm[t] = v;
    out[NG * NC + t] = v;
}
__global__ void k_y(const float* __restrict__ Wlin, const float* __restrict__ blin,
                    float* __restrict__ out) {
    int t = blockIdx.x * blockDim.x + threadIdx.x;
    if (t >= NG * NC) return;
    int g = t / NC, c = t % NC;
    float s = blin[c];
    const float* gm = g_gm + g * HD;
#pragma unroll 8
    for (int k = 0; k < HD; k++) s = fmaf(gm[k], Wlin[k * NC + c], s);
    out[t] = s;
}

// ---------------- launch ----------------
extern "C" void kernel_launch(void* const* d_in, const int* in_sizes, int n_in,
                              void* d_out, int out_size) {
    const float* x     = (const float*)d_in[0];
    const int*   ei    = (const int*)d_in[1];
    const int*   src   = ei;
    const int*   dst   = ei + NE;
    const int*   batch = (const int*)d_in[2];
    const float* gh    = (const float*)d_in[3];
    const float* W0    = (const float*)d_in[4];
    const float* b0    = (const float*)d_in[5];
    const float* Ws    = (const float*)d_in[6];
    const float* bs    = (const float*)d_in[7];
    const float* Wlin  = (const float*)d_in[8];
    const float* blin  = (const float*)d_in[9];
    float* out = (float*)d_out;

    dim3 ggrid((NN + 127) / 128, HD / 128);
    const int propBlocks  = (NN + 3) / 4;
    const int propxBlocks = (NN + 7) / 8;
    const int nsb = (NN + SCAN_B - 1) / SCAN_B;
    const int splitTotal = FD * HD + NL * HD * HD;

    k_init<<<(NN + 255) / 256, 256>>>();
    k_count<<<(NE + 255) / 256, 256>>>(dst, batch);
    k_scan1<<<nsb, SCAN_B>>>();
    k_bsplit<<<(splitTotal + 255) / 256, 256>>>(W0, Ws);
    k_scan2p<<<1, 256>>>(nsb);
    k_scan3<<<nsb, SCAN_B>>>();
    k_scatter<<<(NE + 255) / 256, 256>>>(src, dst);
    k_rgemm<<<dim3(2, NL), 256>>>(gh, Ws);

    // layer 0: z = P x (narrow) ; h0 = z @ W0 + b0
    k_prop_x<<<propxBlocks, 256>>>(x);
    k_gemm<FD, -1><<<ggrid, 256>>>(nullptr, b0);

    // hidden layers: t = h @ Ws[l] + R_l[batch] ; h = relu(P t + bs[l])
    k_gemm<HD, 0><<<ggrid, 256>>>(batch, nullptr);
    k_prop<<<propBlocks, 256>>>(bs + 0 * HD);
    k_gemm<HD, 1><<<ggrid, 256>>>(batch, nullptr);
    k_prop<<<propBlocks, 256>>>(bs + 1 * HD);
    k_gemm<HD, 2><<<ggrid, 256>>>(batch, nullptr);
    k_prop<<<propBlocks, 256>>>(bs + 2 * HD);

    const int poolWarps = (NN + POOL_NPW - 1) / POOL_NPW;
    k_pool_accum<<<(poolWarps * 32 + 255) / 256, 256>>>(batch);
    k_pool_final<<<(NG * HD + 255) / 256, 256>>>(gh, out);
    k_y<<<(NG * NC + 255) / 256, 256>>>(Wlin, blin, out);
}

// round 12
// speedup vs baseline: 1.0693x; 1.0693x over previous
#include <cuda_runtime.h>
#include <cstdint>

static const int NN = 50000;
static const int NE = 800000;
static const int FD = 128;
static const int HD = 256;
static const int NG = 128;
static const int NC = 10;
static const int NL = 3;

// Scratch
__device__ float    g_h[(long long)NN * HD];
__device__ float    g_z[(long long)NN * HD];
__device__ float    g_inv[NN];
__device__ int      g_deg[NN];
__device__ int      g_rowptr[NN + 1];
__device__ int      g_pos[NN];
__device__ int      g_csrc[NE];
__device__ int      g_bsum[256];
__device__ int      g_boff[256];
__device__ float    g_R[NL * NG * HD];
__device__ unsigned g_Bsplit[(FD * HD + NL * HD * HD) * 2];
__device__ float    g_gmsum[NG * HD];
__device__ int      g_cnt[NG];

// ---------------- init ----------------
__global__ void k_init() {
    int i = blockIdx.x * blockDim.x + threadIdx.x;
    if (i < NN) g_deg[i] = 0;
    if (i < NG * HD) g_gmsum[i] = 0.f;
    if (i < NG) g_cnt[i] = 0;
}
__global__ void k_count(const int* __restrict__ dst, const int* __restrict__ batch) {
    int e = blockIdx.x * blockDim.x + threadIdx.x;
    if (e < NE) atomicAdd(&g_deg[dst[e]], 1);
    if (e < NN) atomicAdd(&g_cnt[batch[e]], 1);
}

// ---------------- TF32 helpers ----------------
__device__ __forceinline__ unsigned f2tf(float f) {
    unsigned u;
    asm("cvt.rna.tf32.f32 %0, %1;" : "=r"(u) : "f"(f));
    return u;
}
__device__ __forceinline__ void split_tf32(float f, unsigned& hi, unsigned& lo) {
    hi = f2tf(f);
    lo = f2tf(f - __uint_as_float(hi));
}
__device__ __forceinline__ void mma_tf32(float4& c, const unsigned a[4], const unsigned b[2]) {
    asm volatile(
        "mma.sync.aligned.m16n8k8.row.col.f32.tf32.tf32.f32 "
        "{%0,%1,%2,%3}, {%4,%5,%6,%7}, {%8,%9}, {%0,%1,%2,%3};"
        : "+f"(c.x), "+f"(c.y), "+f"(c.z), "+f"(c.w)
        : "r"(a[0]), "r"(a[1]), "r"(a[2]), "r"(a[3]), "r"(b[0]), "r"(b[1]));
}

// ---------------- weight pre-split ----------------
__global__ void k_bsplit(const float* __restrict__ W0, const float* __restrict__ Ws) {
    int i = blockIdx.x * blockDim.x + threadIdx.x;
    const int total = FD * HD + NL * HD * HD;
    if (i >= total) return;
    float v = (i < FD * HD) ? W0[i] : Ws[i - FD * HD];
    unsigned hi, lo;
    split_tf32(v, hi, lo);
    g_Bsplit[2 * i]     = hi;
    g_Bsplit[2 * i + 1] = lo;
}

// ---------------- CSR build ----------------
#define SCAN_B 256
__global__ void k_scan1() {
    __shared__ int sh[SCAN_B];
    int i = blockIdx.x * SCAN_B + threadIdx.x;
    int v = (i < NN) ? g_deg[i] : 0;
    sh[threadIdx.x] = v;
    __syncthreads();
    for (int s = SCAN_B / 2; s > 0; s >>= 1) {
        if (threadIdx.x < s) sh[threadIdx.x] += sh[threadIdx.x + s];
        __syncthreads();
    }
    if (threadIdx.x == 0) g_bsum[blockIdx.x] = sh[0];
}
__global__ void k_scan2p(int nblocks) {
    __shared__ int sh[256];
    int t = threadIdx.x;
    int v = (t < nblocks) ? g_bsum[t] : 0;
    sh[t] = v;
    __syncthreads();
    for (int s = 1; s < 256; s <<= 1) {
        int u = (t >= s) ? sh[t - s] : 0;
        __syncthreads();
        sh[t] += u;
        __syncthreads();
    }
    if (t < nblocks) g_boff[t] = sh[t] - v;
    if (t == 255) g_rowptr[NN] = sh[255];
}
__global__ void k_scan3() {
    __shared__ int sh[SCAN_B];
    int i = blockIdx.x * SCAN_B + threadIdx.x;
    int v = (i < NN) ? g_deg[i] : 0;
    sh[threadIdx.x] = v;
    __syncthreads();
    for (int s = 1; s < SCAN_B; s <<= 1) {
        int t = (threadIdx.x >= s) ? sh[threadIdx.x - s] : 0;
        __syncthreads();
        sh[threadIdx.x] += t;
        __syncthreads();
    }
    if (i < NN) {
        int excl = g_boff[blockIdx.x] + sh[threadIdx.x] - v;
        g_rowptr[i] = excl;
        g_pos[i] = excl;
        g_inv[i] = rsqrtf((float)(v + 1));
    }
}
__global__ void k_scatter(const int* __restrict__ src, const int* __restrict__ dst) {
    int e = blockIdx.x * blockDim.x + threadIdx.x;
    if (e >= NE) return;
    int d = dst[e];
    int slot = atomicAdd(&g_pos[d], 1);
    g_csrc[slot] = src[e];
}

// ---------------- small GEMM: g_R[l] = gh @ Ws[l] ----------------
__global__ __launch_bounds__(256)
void k_rgemm(const float* __restrict__ gh, const float* __restrict__ Ws) {
    __shared__ float Ag[128 * 36];
    __shared__ float Bg[32 * 132];
    const float* B = Ws + (size_t)blockIdx.y * HD * HD;
    const int colBase = blockIdx.x * 128;
    const int tid = threadIdx.x;
    const int tx = tid & 15, ty = tid >> 4;
    float acc[8][8];
#pragma unroll
    for (int i = 0; i < 8; i++)
#pragma unroll
        for (int j = 0; j < 8; j++) acc[i][j] = 0.f;

    const int ar = tid >> 1, ak = (tid & 1) * 16;
    const int br = tid >> 3, bc = (tid & 7) * 16;
    for (int kt = 0; kt < HD; kt += 32) {
#pragma unroll
        for (int q = 0; q < 4; q++) {
            float4 v = *(const float4*)(gh + (size_t)ar * HD + kt + ak + 4 * q);
            *(float4*)&Ag[ar * 36 + ak + 4 * q] = v;
            float4 w = *(const float4*)(B + (size_t)(kt + br) * HD + colBase + bc + 4 * q);
            *(float4*)&Bg[br * 132 + bc + 4 * q] = w;
        }
        __syncthreads();
#pragma unroll
        for (int kk = 0; kk < 32; kk++) {
            float a[8], b[8];
#pragma unroll
            for (int i = 0; i < 8; i++) a[i] = Ag[(ty * 8 + i) * 36 + kk];
            *(float4*)(b)     = *(const float4*)&Bg[kk * 132 + tx * 8];
            *(float4*)(b + 4) = *(const float4*)&Bg[kk * 132 + tx * 8 + 4];
#pragma unroll
            for (int i = 0; i < 8; i++)
#pragma unroll
                for (int j = 0; j < 8; j++) acc[i][j] = fmaf(a[i], b[j], acc[i][j]);
        }
        __syncthreads();
    }
    float* outp = g_R + (size_t)blockIdx.y * NG * HD;
#pragma unroll
    for (int i = 0; i < 8; i++)
#pragma unroll
        for (int j = 0; j < 2; j++)
            *(float4*)(outp + (size_t)(ty * 8 + i) * HD + colBase + tx * 8 + 4 * j) =
                make_float4(acc[i][4 * j], acc[i][4 * j + 1], acc[i][4 * j + 2], acc[i][4 * j + 3]);
}

// ---------------- main tensor GEMM (Round-10 core + A prefetch) ----------------
// LIDX < 0: A = g_z (N x KD), out = g_h, epilogue += bias[col], B = W0 split
// LIDX >= 0: A = g_h (N x 256), out = g_z, epilogue += g_R[LIDX][batch[row]], B = Ws[LIDX] split
#define AS_STRIDE 36
#define BS2_W 264
template<int KD, int LIDX>
__global__ __launch_bounds__(256, 2)
void k_gemm(const int* __restrict__ batch, const float* __restrict__ bias) {
    __shared__ float    As[128 * AS_STRIDE];
    __shared__ unsigned Bs[16 * BS2_W];
    const int tid  = threadIdx.x;
    const int lane = tid & 31;
    const int warp = tid >> 5;
    const int wm = warp >> 1;
    const int wn = warp & 1;
    const int rowBase = blockIdx.x * 128;
    const int colBase = blockIdx.y * 128;

    const int arow   = tid >> 1;
    const int akBase = (tid & 1) * 16;
    const int bk  = tid >> 4;          // 0..15
    const int bq  = (tid & 15) * 4;

    const int aRowG = rowBase + arow;
    const bool rowOK = (aRowG < NN);
    const float* aPtr = (LIDX < 0 ? (const float*)g_z : (const float*)g_h) + (size_t)aRowG * KD;
    float* outBase = (LIDX < 0 ? g_h : g_z);
    const unsigned* B2 = g_Bsplit + (LIDX < 0 ? 0 : ((size_t)FD * HD + (size_t)LIDX * HD * HD) * 2);

    float4 acc[2][8];
#pragma unroll
    for (int i = 0; i < 2; i++)
#pragma unroll
        for (int j = 0; j < 8; j++) acc[i][j] = make_float4(0.f, 0.f, 0.f, 0.f);

    // A prefetch registers (current tile)
    float4 aR[4];
#pragma unroll
    for (int q = 0; q < 4; q++) aR[q] = make_float4(0.f, 0.f, 0.f, 0.f);
    if (rowOK) {
#pragma unroll
        for (int q = 0; q < 4; q++) aR[q] = *(const float4*)(aPtr + akBase + 4 * q);
    }

    for (int kt = 0; kt < KD; kt += 32) {
        // ---- stage A (from prefetched regs) ----
#pragma unroll
        for (int q = 0; q < 4; q++)
            *(float4*)&As[arow * AS_STRIDE + akBase + 4 * q] = aR[q];

#pragma unroll
        for (int half = 0; half < 2; half++) {
            // ---- stage pre-split B (16 k rows) ----
            {
                const unsigned* bg = B2 + ((size_t)(kt + half * 16 + bk) * HD + colBase) * 2 + bq;
#pragma unroll
                for (int i = 0; i < 4; i++) {
                    uint4 v = *(const uint4*)(bg + i * 64);
                    *(uint4*)&Bs[bk * BS2_W + bq + i * 64] = v;
                }
            }
            __syncthreads();

            // issue next-tile A loads early (latency hidden under both compute halves)
            if (half == 0 && kt + 32 < KD && rowOK) {
#pragma unroll
                for (int q = 0; q < 4; q++)
                    aR[q] = *(const float4*)(aPtr + kt + 32 + akBase + 4 * q);
            }

#pragma unroll
            for (int k8 = 0; k8 < 2; k8++) {
                const int kk  = k8 * 8 + (lane & 3);
                const int kkA = half * 16 + kk;
                unsigned ah[2][4], al[2][4];
#pragma unroll
                for (int i = 0; i < 2; i++) {
                    int r = wm * 32 + i * 16 + (lane >> 2);
                    float v0 = As[r * AS_STRIDE + kkA];
                    float v1 = As[(r + 8) * AS_STRIDE + kkA];
                    float v2 = As[r * AS_STRIDE + kkA + 4];
                    float v3 = As[(r + 8) * AS_STRIDE + kkA + 4];
                    split_tf32(v0, ah[i][0], al[i][0]);
                    split_tf32(v1, ah[i][1], al[i][1]);
                    split_tf32(v2, ah[i][2], al[i][2]);
                    split_tf32(v3, ah[i][3], al[i][3]);
                }
#pragma unroll
                for (int h = 0; h < 2; h++) {
                    unsigned bh[4][2], bl[4][2];
#pragma unroll
                    for (int j = 0; j < 4; j++) {
                        int c = wn * 64 + h * 32 + j * 8 + (lane >> 2);
                        uint2 p0 = *(const uint2*)&Bs[kk * BS2_W + c * 2];
                        uint2 p1 = *(const uint2*)&Bs[(kk + 4) * BS2_W + c * 2];
                        bh[j][0] = p0.x; bl[j][0] = p0.y;
                        bh[j][1] = p1.x; bl[j][1] = p1.y;
                    }
#pragma unroll
                    for (int i = 0; i < 2; i++)
#pragma unroll
                        for (int j = 0; j < 4; j++) {
                            float4& c4 = acc[i][h * 4 + j];
                            mma_tf32(c4, ah[i], bh[j]);
                            mma_tf32(c4, ah[i], bl[j]);
                            mma_tf32(c4, al[i], bh[j]);
                        }
                }
            }
            __syncthreads();
        }
    }

    // ---- epilogue ----
#pragma unroll
    for (int i = 0; i < 2; i++) {
        int r0 = rowBase + wm * 32 + i * 16 + (lane >> 2);
        const float* Ra = nullptr;
        const float* Rb = nullptr;
        if (LIDX >= 0) {
            if (r0 < NN)     Ra = g_R + (size_t)LIDX * NG * HD + (size_t)batch[r0] * HD;
            if (r0 + 8 < NN) Rb = g_R + (size_t)LIDX * NG * HD + (size_t)batch[r0 + 8] * HD;
        }
#pragma unroll
        for (int j = 0; j < 8; j++) {
            int c = colBase + wn * 64 + j * 8 + 2 * (lane & 3);
            float4 v = acc[i][j];
            float2 bc2 = make_float2(0.f, 0.f);
            if (LIDX < 0) bc2 = *(const float2*)(bias + c);
            if (r0 < NN) {
                float2 o = make_float2(v.x, v.y);
                if (LIDX >= 0) { float2 r = *(const float2*)(Ra + c); o.x += r.x; o.y += r.y; }
                else           { o.x += bc2.x; o.y += bc2.y; }
                *(float2*)(outBase + (size_t)r0 * HD + c) = o;
            }
            if (r0 + 8 < NN) {
                float2 o = make_float2(v.z, v.w);
                if (LIDX >= 0) { float2 r = *(const float2*)(Rb + c); o.x += r.x; o.y += r.y; }
                else           { o.x += bc2.x; o.y += bc2.y; }
                *(float2*)(outBase + (size_t)(r0 + 8) * HD + c) = o;
            }
        }
    }
}

// ---------------- propagation ----------------
__device__ __forceinline__ void acc4(float4& acc, const float4& u, float wt) {
    acc.x = fmaf(u.x, wt, acc.x);
    acc.y = fmaf(u.y, wt, acc.y);
    acc.z = fmaf(u.z, wt, acc.z);
    acc.w = fmaf(u.w, wt, acc.w);
}

// z = P x  (N x 128). One warp per node.
__global__ __launch_bounds__(256)
void k_prop_x(const float* __restrict__ x) {
    int node = blockIdx.x * 8 + (threadIdx.x >> 5);
    int lane = threadIdx.x & 31;
    if (node >= NN) return;
    int off = lane * 4;
    float invd = g_inv[node];
    float sq = invd * invd;
    float4 h0 = *(const float4*)(x + (size_t)node * FD + off);
    float4 acc = make_float4(h0.x * sq, h0.y * sq, h0.z * sq, h0.w * sq);
    int e   = g_rowptr[node];
    int end = g_rowptr[node + 1];
    for (; e + 8 <= end; e += 8) {
        int s[8];
        float wt[8];
        float4 u[8];
#pragma unroll
        for (int q = 0; q < 8; q++) s[q] = g_csrc[e + q];
#pragma unroll
        for (int q = 0; q < 8; q++) u[q] = *(const float4*)(x + (size_t)s[q] * FD + off);
#pragma unroll
        for (int q = 0; q < 8; q++) wt[q] = g_inv[s[q]] * invd;
#pragma unroll
        for (int q = 0; q < 8; q++) acc4(acc, u[q], wt[q]);
    }
    for (; e < end; e++) {
        int s0 = g_csrc[e];
        float w0 = g_inv[s0] * invd;
        float4 u0 = *(const float4*)(x + (size_t)s0 * FD + off);
        acc4(acc, u0, w0);
    }
    *(float4*)(g_z + (size_t)node * FD + off) = acc;
}

// h = relu(P t + bias), t in g_z (N x 256), out g_h. 2 warps per node.
__global__ __launch_bounds__(256)
void k_prop(const float* __restrict__ bias) {
    int node = blockIdx.x * 4 + (threadIdx.x >> 6);
    int half = (threadIdx.x >> 5) & 1;
    int lane = threadIdx.x & 31;
    if (node >= NN) return;
    int off = half * 128 + lane * 4;
    float invd = g_inv[node];
    float sq = invd * invd;
    float4 h0 = *(const float4*)(g_z + (size_t)node * HD + off);
    float4 b0 = *(const float4*)(bias + off);
    float4 acc = make_float4(fmaf(h0.x, sq, b0.x), fmaf(h0.y, sq, b0.y),
                             fmaf(h0.z, sq, b0.z), fmaf(h0.w, sq, b0.w));
    int e   = g_rowptr[node];
    int end = g_rowptr[node + 1];
    for (; e + 8 <= end; e += 8) {
        int s[8];
        float wt[8];
        float4 u[8];
#pragma unroll
        for (int q = 0; q < 8; q++) s[q] = g_csrc[e + q];
#pragma unroll
        for (int q = 0; q < 8; q++) u[q] = *(const float4*)(g_z + (size_t)s[q] * HD + off);
#pragma unroll
        for (int q = 0; q < 8; q++) wt[q] = g_inv[s[q]] * invd;
#pragma unroll
        for (int q = 0; q < 8; q++) acc4(acc, u[q], wt[q]);
    }
    for (; e + 2 <= end; e += 2) {
        int s0 = g_csrc[e], s1 = g_csrc[e + 1];
        float4 u0 = *(const float4*)(g_z + (size_t)s0 * HD + off);
        float4 u1 = *(const float4*)(g_z + (size_t)s1 * HD + off);
        float w0 = g_inv[s0] * invd, w1 = g_inv[s1] * invd;
        acc4(acc, u0, w0);
        acc4(acc, u1, w1);
    }
    if (e < end) {
        int s0 = g_csrc[e];
        float w0 = g_inv[s0] * invd;
        float4 u0 = *(const float4*)(g_z + (size_t)s0 * HD + off);
        acc4(acc, u0, w0);
    }
    acc.x = fmaxf(acc.x, 0.f); acc.y = fmaxf(acc.y, 0.f);
    acc.z = fmaxf(acc.z, 0.f); acc.w = fmaxf(acc.w, 0.f);
    *(float4*)(g_h + (size_t)node * HD + off) = acc;
}

// ---------------- pooling (reads g_h) ----------------
#define POOL_NPW 8
__global__ void k_pool_accum(const int* __restrict__ batch) {
    int w = (blockIdx.x * blockDim.x + threadIdx.x) >> 5;
    int lane = threadIdx.x & 31;
    int n0 = w * POOL_NPW;
    if (n0 >= NN) return;
    int nend = n0 + POOL_NPW;
    if (nend > NN) nend = NN;
    float4 a0 = make_float4(0.f, 0.f, 0.f, 0.f);
    float4 a1 = a0;
    int cur = batch[n0];
    for (int n = n0; n < nend; n++) {
        int b = batch[n];
        if (b != cur) {
            float* gs = g_gmsum + (size_t)cur * HD;
            asm volatile("red.global.add.v4.f32 [%0], {%1,%2,%3,%4};"
                         :: "l"(gs + lane * 4), "f"(a0.x), "f"(a0.y), "f"(a0.z), "f"(a0.w) : "memory");
            asm volatile("red.global.add.v4.f32 [%0], {%1,%2,%3,%4};"
                         :: "l"(gs + 128 + lane * 4), "f"(a1.x), "f"(a1.y), "f"(a1.z), "f"(a1.w) : "memory");
            a0 = make_float4(0.f, 0.f, 0.f, 0.f);
            a1 = a0;
            cur = b;
        }
        float4 v0 = *(const float4*)(g_h + (size_t)n * HD + lane * 4);
        float4 v1 = *(const float4*)(g_h + (size_t)n * HD + 128 + lane * 4);
        a0.x += v0.x; a0.y += v0.y; a0.z += v0.z; a0.w += v0.w;
        a1.x += v1.x; a1.y += v1.y; a1.z += v1.z; a1.w += v1.w;
    }
    float* gs = g_gmsum + (size_t)cur * HD;
    asm volatile("red.global.add.v4.f32 [%0], {%1,%2,%3,%4};"
                 :: "l"(gs + lane * 4), "f"(a0.x), "f"(a0.y), "f"(a0.z), "f"(a0.w) : "memory");
    asm volatile("red.global.add.v4.f32 [%0], {%1,%2,%3,%4};"
                 :: "l"(gs + 128 + lane * 4), "f"(a1.x), "f"(a1.y), "f"(a1.z), "f"(a1.w) : "memory");
}

// ---------------- fused gm + head: one block per graph ----------------
__global__ __launch_bounds__(256)
void k_head(const float* __restrict__ gh, const float* __restrict__ Wlin,
            const float* __restrict__ blin, float* __restrict__ out) {
    __shared__ float gm[HD];
    int g = blockIdx.x;
    int t = threadIdx.x;
    float cnt = (float)max(g_cnt[g], 1);
    float v = g_gmsum[g * HD + t] / cnt + gh[g * HD + t];
    gm[t] = v;
    out[NG * NC + g * HD + t] = v;
    __syncthreads();
    if (t < NC) {
        float s = blin[t];
#pragma unroll 8
        for (int k = 0; k < HD; k++) s = fmaf(gm[k], Wlin[k * NC + t], s);
        out[g * NC + t] = s;
    }
}

// ---------------- launch ----------------
extern "C" void kernel_launch(void* const* d_in, const int* in_sizes, int n_in,
                              void* d_out, int out_size) {
    const float* x     = (const float*)d_in[0];
    const int*   ei    = (const int*)d_in[1];
    const int*   src   = ei;
    const int*   dst   = ei + NE;
    const int*   batch = (const int*)d_in[2];
    const float* gh    = (const float*)d_in[3];
    const float* W0    = (const float*)d_in[4];
    const float* b0    = (const float*)d_in[5];
    const float* Ws    = (const float*)d_in[6];
    const float* bs    = (const float*)d_in[7];
    const float* Wlin  = (const float*)d_in[8];
    const float* blin  = (const float*)d_in[9];
    float* out = (float*)d_out;

    dim3 ggrid((NN + 127) / 128, HD / 128);
    const int propBlocks  = (NN + 3) / 4;
    const int propxBlocks = (NN + 7) / 8;
    const int nsb = (NN + SCAN_B - 1) / SCAN_B;
    const int splitTotal = FD * HD + NL * HD * HD;

    k_init<<<(NN + 255) / 256, 256>>>();
    k_count<<<(NE + 255) / 256, 256>>>(dst, batch);
    k_scan1<<<nsb, SCAN_B>>>();
    k_bsplit<<<(splitTotal + 255) / 256, 256>>>(W0, Ws);
    k_scan2p<<<1, 256>>>(nsb);
    k_scan3<<<nsb, SCAN_B>>>();
    k_scatter<<<(NE + 255) / 256, 256>>>(src, dst);
    k_rgemm<<<dim3(2, NL), 256>>>(gh, Ws);

    // layer 0: z = P x (narrow) ; h0 = z @ W0 + b0
    k_prop_x<<<propxBlocks, 256>>>(x);
    k_gemm<FD, -1><<<ggrid, 256>>>(nullptr, b0);

    // hidden layers: t = h @ Ws[l] + R_l[batch] ; h = relu(P t + bs[l])
    k_gemm<HD, 0><<<ggrid, 256>>>(batch, nullptr);
    k_prop<<<propBlocks, 256>>>(bs + 0 * HD);
    k_gemm<HD, 1><<<ggrid, 256>>>(batch, nullptr);
    k_prop<<<propBlocks, 256>>>(bs + 1 * HD);
    k_gemm<HD, 2><<<ggrid, 256>>>(batch, nullptr);
    k_prop<<<propBlocks, 256>>>(bs + 2 * HD);

    const int poolWarps = (NN + POOL_NPW - 1) / POOL_NPW;
    k_pool_accum<<<(poolWarps * 32 + 255) / 256, 256>>>(batch);
    k_head<<<NG, 256>>>(gh, Wlin, blin, out);
}

// round 13
// speedup vs baseline: 1.1011x; 1.0297x over previous
#include <cuda_runtime.h>
#include <cstdint>

static const int NN = 50000;
static const int NE = 800000;
static const int FD = 128;
static const int HD = 256;
static const int NG = 128;
static const int NC = 10;
static const int NL = 3;

// Scratch
__device__ float    g_h[(long long)NN * HD];
__device__ float    g_z[(long long)NN * HD];
__device__ float    g_inv[NN];
__device__ int      g_deg[NN];
__device__ int      g_rowptr[NN + 1];
__device__ int      g_pos[NN];
__device__ int      g_csrc[NE];
__device__ int      g_bsum[256];
__device__ int      g_boff[256];
__device__ float    g_R[NL * NG * HD];
__device__ unsigned g_Bsplit[(FD * HD + NL * HD * HD) * 2];
__device__ float    g_gmsum[NG * HD];
__device__ int      g_cnt[NG];

// ---------------- init ----------------
__global__ void k_init() {
    int i = blockIdx.x * blockDim.x + threadIdx.x;
    if (i < NN) g_deg[i] = 0;
    if (i < NG * HD) g_gmsum[i] = 0.f;
    if (i < NG) g_cnt[i] = 0;
}
__global__ void k_count(const int* __restrict__ dst, const int* __restrict__ batch) {
    int e = blockIdx.x * blockDim.x + threadIdx.x;
    if (e < NE) atomicAdd(&g_deg[dst[e]], 1);
    if (e < NN) atomicAdd(&g_cnt[batch[e]], 1);
}

// ---------------- TF32 helpers ----------------
__device__ __forceinline__ unsigned f2tf(float f) {
    unsigned u;
    asm("cvt.rna.tf32.f32 %0, %1;" : "=r"(u) : "f"(f));
    return u;
}
__device__ __forceinline__ void split_tf32(float f, unsigned& hi, unsigned& lo) {
    hi = f2tf(f);
    lo = f2tf(f - __uint_as_float(hi));
}
__device__ __forceinline__ void mma_tf32(float4& c, const unsigned a[4], const unsigned b[2]) {
    asm volatile(
        "mma.sync.aligned.m16n8k8.row.col.f32.tf32.tf32.f32 "
        "{%0,%1,%2,%3}, {%4,%5,%6,%7}, {%8,%9}, {%0,%1,%2,%3};"
        : "+f"(c.x), "+f"(c.y), "+f"(c.z), "+f"(c.w)
        : "r"(a[0]), "r"(a[1]), "r"(a[2]), "r"(a[3]), "r"(b[0]), "r"(b[1]));
}

// ---------------- weight pre-split ----------------
__global__ void k_bsplit(const float* __restrict__ W0, const float* __restrict__ Ws) {
    int i = blockIdx.x * blockDim.x + threadIdx.x;
    const int total = FD * HD + NL * HD * HD;
    if (i >= total) return;
    float v = (i < FD * HD) ? W0[i] : Ws[i - FD * HD];
    unsigned hi, lo;
    split_tf32(v, hi, lo);
    g_Bsplit[2 * i]     = hi;
    g_Bsplit[2 * i + 1] = lo;
}

// ---------------- CSR build ----------------
#define SCAN_B 256
__global__ void k_scan1() {
    __shared__ int sh[SCAN_B];
    int i = blockIdx.x * SCAN_B + threadIdx.x;
    int v = (i < NN) ? g_deg[i] : 0;
    sh[threadIdx.x] = v;
    __syncthreads();
    for (int s = SCAN_B / 2; s > 0; s >>= 1) {
        if (threadIdx.x < s) sh[threadIdx.x] += sh[threadIdx.x + s];
        __syncthreads();
    }
    if (threadIdx.x == 0) g_bsum[blockIdx.x] = sh[0];
}
__global__ void k_scan2p(int nblocks) {
    __shared__ int sh[256];
    int t = threadIdx.x;
    int v = (t < nblocks) ? g_bsum[t] : 0;
    sh[t] = v;
    __syncthreads();
    for (int s = 1; s < 256; s <<= 1) {
        int u = (t >= s) ? sh[t - s] : 0;
        __syncthreads();
        sh[t] += u;
        __syncthreads();
    }
    if (t < nblocks) g_boff[t] = sh[t] - v;
    if (t == 255) g_rowptr[NN] = sh[255];
}
__global__ void k_scan3() {
    __shared__ int sh[SCAN_B];
    int i = blockIdx.x * SCAN_B + threadIdx.x;
    int v = (i < NN) ? g_deg[i] : 0;
    sh[threadIdx.x] = v;
    __syncthreads();
    for (int s = 1; s < SCAN_B; s <<= 1) {
        int t = (threadIdx.x >= s) ? sh[threadIdx.x - s] : 0;
        __syncthreads();
        sh[threadIdx.x] += t;
        __syncthreads();
    }
    if (i < NN) {
        int excl = g_boff[blockIdx.x] + sh[threadIdx.x] - v;
        g_rowptr[i] = excl;
        g_pos[i] = excl;
        g_inv[i] = rsqrtf((float)(v + 1));
    }
}
__global__ void k_scatter(const int* __restrict__ src, const int* __restrict__ dst) {
    int e = blockIdx.x * blockDim.x + threadIdx.x;
    if (e >= NE) return;
    int d = dst[e];
    int slot = atomicAdd(&g_pos[d], 1);
    g_csrc[slot] = src[e];
}

// ---------------- small GEMM: g_R[l] = gh @ Ws[l] ----------------
__global__ __launch_bounds__(256)
void k_rgemm(const float* __restrict__ gh, const float* __restrict__ Ws) {
    __shared__ float Ag[128 * 36];
    __shared__ float Bg[32 * 132];
    const float* B = Ws + (size_t)blockIdx.y * HD * HD;
    const int colBase = blockIdx.x * 128;
    const int tid = threadIdx.x;
    const int tx = tid & 15, ty = tid >> 4;
    float acc[8][8];
#pragma unroll
    for (int i = 0; i < 8; i++)
#pragma unroll
        for (int j = 0; j < 8; j++) acc[i][j] = 0.f;

    const int ar = tid >> 1, ak = (tid & 1) * 16;
    const int br = tid >> 3, bc = (tid & 7) * 16;
    for (int kt = 0; kt < HD; kt += 32) {
#pragma unroll
        for (int q = 0; q < 4; q++) {
            float4 v = *(const float4*)(gh + (size_t)ar * HD + kt + ak + 4 * q);
            *(float4*)&Ag[ar * 36 + ak + 4 * q] = v;
            float4 w = *(const float4*)(B + (size_t)(kt + br) * HD + colBase + bc + 4 * q);
            *(float4*)&Bg[br * 132 + bc + 4 * q] = w;
        }
        __syncthreads();
#pragma unroll
        for (int kk = 0; kk < 32; kk++) {
            float a[8], b[8];
#pragma unroll
            for (int i = 0; i < 8; i++) a[i] = Ag[(ty * 8 + i) * 36 + kk];
            *(float4*)(b)     = *(const float4*)&Bg[kk * 132 + tx * 8];
            *(float4*)(b + 4) = *(const float4*)&Bg[kk * 132 + tx * 8 + 4];
#pragma unroll
            for (int i = 0; i < 8; i++)
#pragma unroll
                for (int j = 0; j < 8; j++) acc[i][j] = fmaf(a[i], b[j], acc[i][j]);
        }
        __syncthreads();
    }
    float* outp = g_R + (size_t)blockIdx.y * NG * HD;
#pragma unroll
    for (int i = 0; i < 8; i++)
#pragma unroll
        for (int j = 0; j < 2; j++)
            *(float4*)(outp + (size_t)(ty * 8 + i) * HD + colBase + tx * 8 + 4 * j) =
                make_float4(acc[i][4 * j], acc[i][4 * j + 1], acc[i][4 * j + 2], acc[i][4 * j + 3]);
}

// ---------------- main tensor GEMM (Round-10 core, byte-exact) ----------------
// LIDX < 0: A = g_z (N x KD), out = g_h, epilogue += bias[col], B = W0 split
// LIDX >= 0: A = g_h (N x 256), out = g_z, epilogue += g_R[LIDX][batch[row]], B = Ws[LIDX] split
#define AS_STRIDE 36
#define BS2_W 264
template<int KD, int LIDX>
__global__ __launch_bounds__(256, 2)
void k_gemm(const int* __restrict__ batch, const float* __restrict__ bias) {
    __shared__ float    As[128 * AS_STRIDE];
    __shared__ unsigned Bs[16 * BS2_W];
    const int tid  = threadIdx.x;
    const int lane = tid & 31;
    const int warp = tid >> 5;
    const int wm = warp >> 1;
    const int wn = warp & 1;
    const int rowBase = blockIdx.x * 128;
    const int colBase = blockIdx.y * 128;

    const int arow   = tid >> 1;
    const int akBase = (tid & 1) * 16;
    const int bk  = tid >> 4;          // 0..15
    const int bq  = (tid & 15) * 4;

    const int aRowG = rowBase + arow;
    const bool rowOK = (aRowG < NN);
    const float* aPtr = (LIDX < 0 ? (const float*)g_z : (const float*)g_h) + (size_t)aRowG * KD;
    float* outBase = (LIDX < 0 ? g_h : g_z);
    const unsigned* B2 = g_Bsplit + (LIDX < 0 ? 0 : ((size_t)FD * HD + (size_t)LIDX * HD * HD) * 2);

    float4 acc[2][8];
#pragma unroll
    for (int i = 0; i < 2; i++)
#pragma unroll
        for (int j = 0; j < 8; j++) acc[i][j] = make_float4(0.f, 0.f, 0.f, 0.f);

    for (int kt = 0; kt < KD; kt += 32) {
        // ---- stage A (32 k deep) ----
#pragma unroll
        for (int q = 0; q < 4; q++) {
            int k = akBase + q * 4;
            float4 v = make_float4(0.f, 0.f, 0.f, 0.f);
            if (rowOK) v = *(const float4*)(aPtr + kt + k);
            *(float4*)&As[arow * AS_STRIDE + k] = v;
        }
#pragma unroll
        for (int half = 0; half < 2; half++) {
            // ---- stage pre-split B (16 k rows) ----
            {
                const unsigned* bg = B2 + ((size_t)(kt + half * 16 + bk) * HD + colBase) * 2 + bq;
#pragma unroll
                for (int i = 0; i < 4; i++) {
                    uint4 v = *(const uint4*)(bg + i * 64);
                    *(uint4*)&Bs[bk * BS2_W + bq + i * 64] = v;
                }
            }
            __syncthreads();

#pragma unroll
            for (int k8 = 0; k8 < 2; k8++) {
                const int kk  = k8 * 8 + (lane & 3);
                const int kkA = half * 16 + kk;
                unsigned ah[2][4], al[2][4];
#pragma unroll
                for (int i = 0; i < 2; i++) {
                    int r = wm * 32 + i * 16 + (lane >> 2);
                    float v0 = As[r * AS_STRIDE + kkA];
                    float v1 = As[(r + 8) * AS_STRIDE + kkA];
                    float v2 = As[r * AS_STRIDE + kkA + 4];
                    float v3 = As[(r + 8) * AS_STRIDE + kkA + 4];
                    split_tf32(v0, ah[i][0], al[i][0]);
                    split_tf32(v1, ah[i][1], al[i][1]);
                    split_tf32(v2, ah[i][2], al[i][2]);
                    split_tf32(v3, ah[i][3], al[i][3]);
                }
#pragma unroll
                for (int h = 0; h < 2; h++) {
                    unsigned bh[4][2], bl[4][2];
#pragma unroll
                    for (int j = 0; j < 4; j++) {
                        int c = wn * 64 + h * 32 + j * 8 + (lane >> 2);
                        uint2 p0 = *(const uint2*)&Bs[kk * BS2_W + c * 2];
                        uint2 p1 = *(const uint2*)&Bs[(kk + 4) * BS2_W + c * 2];
                        bh[j][0] = p0.x; bl[j][0] = p0.y;
                        bh[j][1] = p1.x; bl[j][1] = p1.y;
                    }
#pragma unroll
                    for (int i = 0; i < 2; i++)
#pragma unroll
                        for (int j = 0; j < 4; j++) {
                            float4& c4 = acc[i][h * 4 + j];
                            mma_tf32(c4, ah[i], bh[j]);
                            mma_tf32(c4, ah[i], bl[j]);
                            mma_tf32(c4, al[i], bh[j]);
                        }
                }
            }
            __syncthreads();
        }
    }

    // ---- epilogue ----
#pragma unroll
    for (int i = 0; i < 2; i++) {
        int r0 = rowBase + wm * 32 + i * 16 + (lane >> 2);
        const float* Ra = nullptr;
        const float* Rb = nullptr;
        if (LIDX >= 0) {
            if (r0 < NN)     Ra = g_R + (size_t)LIDX * NG * HD + (size_t)batch[r0] * HD;
            if (r0 + 8 < NN) Rb = g_R + (size_t)LIDX * NG * HD + (size_t)batch[r0 + 8] * HD;
        }
#pragma unroll
        for (int j = 0; j < 8; j++) {
            int c = colBase + wn * 64 + j * 8 + 2 * (lane & 3);
            float4 v = acc[i][j];
            float2 bc2 = make_float2(0.f, 0.f);
            if (LIDX < 0) bc2 = *(const float2*)(bias + c);
            if (r0 < NN) {
                float2 o = make_float2(v.x, v.y);
                if (LIDX >= 0) { float2 r = *(const float2*)(Ra + c); o.x += r.x; o.y += r.y; }
                else           { o.x += bc2.x; o.y += bc2.y; }
                *(float2*)(outBase + (size_t)r0 * HD + c) = o;
            }
            if (r0 + 8 < NN) {
                float2 o = make_float2(v.z, v.w);
                if (LIDX >= 0) { float2 r = *(const float2*)(Rb + c); o.x += r.x; o.y += r.y; }
                else           { o.x += bc2.x; o.y += bc2.y; }
                *(float2*)(outBase + (size_t)(r0 + 8) * HD + c) = o;
            }
        }
    }
}

// ---------------- propagation ----------------
__device__ __forceinline__ void acc4(float4& acc, const float4& u, float wt) {
    acc.x = fmaf(u.x, wt, acc.x);
    acc.y = fmaf(u.y, wt, acc.y);
    acc.z = fmaf(u.z, wt, acc.z);
    acc.w = fmaf(u.w, wt, acc.w);
}

// z = P x  (N x 128). One warp per node.
__global__ __launch_bounds__(256)
void k_prop_x(const float* __restrict__ x) {
    int node = blockIdx.x * 8 + (threadIdx.x >> 5);
    int lane = threadIdx.x & 31;
    if (node >= NN) return;
    int off = lane * 4;
    float invd = g_inv[node];
    float sq = invd * invd;
    float4 h0 = *(const float4*)(x + (size_t)node * FD + off);
    float4 acc = make_float4(h0.x * sq, h0.y * sq, h0.z * sq, h0.w * sq);
    int e   = g_rowptr[node];
    int end = g_rowptr[node + 1];
    for (; e + 8 <= end; e += 8) {
        int s[8];
        float wt[8];
        float4 u[8];
#pragma unroll
        for (int q = 0; q < 8; q++) s[q] = g_csrc[e + q];
#pragma unroll
        for (int q = 0; q < 8; q++) u[q] = *(const float4*)(x + (size_t)s[q] * FD + off);
#pragma unroll
        for (int q = 0; q < 8; q++) wt[q] = g_inv[s[q]] * invd;
#pragma unroll
        for (int q = 0; q < 8; q++) acc4(acc, u[q], wt[q]);
    }
    for (; e < end; e++) {
        int s0 = g_csrc[e];
        float w0 = g_inv[s0] * invd;
        float4 u0 = *(const float4*)(x + (size_t)s0 * FD + off);
        acc4(acc, u0, w0);
    }
    *(float4*)(g_z + (size_t)node * FD + off) = acc;
}

// h = relu(P t + bias), t in g_z (N x 256), out g_h. 2 warps per node.
__global__ __launch_bounds__(256)
void k_prop(const float* __restrict__ bias) {
    int node = blockIdx.x * 4 + (threadIdx.x >> 6);
    int half = (threadIdx.x >> 5) & 1;
    int lane = threadIdx.x & 31;
    if (node >= NN) return;
    int off = half * 128 + lane * 4;
    float invd = g_inv[node];
    float sq = invd * invd;
    float4 h0 = *(const float4*)(g_z + (size_t)node * HD + off);
    float4 b0 = *(const float4*)(bias + off);
    float4 acc = make_float4(fmaf(h0.x, sq, b0.x), fmaf(h0.y, sq, b0.y),
                             fmaf(h0.z, sq, b0.z), fmaf(h0.w, sq, b0.w));
    int e   = g_rowptr[node];
    int end = g_rowptr[node + 1];
    for (; e + 8 <= end; e += 8) {
        int s[8];
        float wt[8];
        float4 u[8];
#pragma unroll
        for (int q = 0; q < 8; q++) s[q] = g_csrc[e + q];
#pragma unroll
        for (int q = 0; q < 8; q++) u[q] = *(const float4*)(g_z + (size_t)s[q] * HD + off);
#pragma unroll
        for (int q = 0; q < 8; q++) wt[q] = g_inv[s[q]] * invd;
#pragma unroll
        for (int q = 0; q < 8; q++) acc4(acc, u[q], wt[q]);
    }
    for (; e + 2 <= end; e += 2) {
        int s0 = g_csrc[e], s1 = g_csrc[e + 1];
        float4 u0 = *(const float4*)(g_z + (size_t)s0 * HD + off);
        float4 u1 = *(const float4*)(g_z + (size_t)s1 * HD + off);
        float w0 = g_inv[s0] * invd, w1 = g_inv[s1] * invd;
        acc4(acc, u0, w0);
        acc4(acc, u1, w1);
    }
    if (e < end) {
        int s0 = g_csrc[e];
        float w0 = g_inv[s0] * invd;
        float4 u0 = *(const float4*)(g_z + (size_t)s0 * HD + off);
        acc4(acc, u0, w0);
    }
    acc.x = fmaxf(acc.x, 0.f); acc.y = fmaxf(acc.y, 0.f);
    acc.z = fmaxf(acc.z, 0.f); acc.w = fmaxf(acc.w, 0.f);
    *(float4*)(g_h + (size_t)node * HD + off) = acc;
}

// ---------------- pooling (reads g_h) ----------------
#define POOL_NPW 8
__global__ void k_pool_accum(const int* __restrict__ batch) {
    int w = (blockIdx.x * blockDim.x + threadIdx.x) >> 5;
    int lane = threadIdx.x & 31;
    int n0 = w * POOL_NPW;
    if (n0 >= NN) return;
    int nend = n0 + POOL_NPW;
    if (nend > NN) nend = NN;
    float4 a0 = make_float4(0.f, 0.f, 0.f, 0.f);
    float4 a1 = a0;
    int cur = batch[n0];
    for (int n = n0; n < nend; n++) {
        int b = batch[n];
        if (b != cur) {
            float* gs = g_gmsum + (size_t)cur * HD;
            asm volatile("red.global.add.v4.f32 [%0], {%1,%2,%3,%4};"
                         :: "l"(gs + lane * 4), "f"(a0.x), "f"(a0.y), "f"(a0.z), "f"(a0.w) : "memory");
            asm volatile("red.global.add.v4.f32 [%0], {%1,%2,%3,%4};"
                         :: "l"(gs + 128 + lane * 4), "f"(a1.x), "f"(a1.y), "f"(a1.z), "f"(a1.w) : "memory");
            a0 = make_float4(0.f, 0.f, 0.f, 0.f);
            a1 = a0;
            cur = b;
        }
        float4 v0 = *(const float4*)(g_h + (size_t)n * HD + lane * 4);
        float4 v1 = *(const float4*)(g_h + (size_t)n * HD + 128 + lane * 4);
        a0.x += v0.x; a0.y += v0.y; a0.z += v0.z; a0.w += v0.w;
        a1.x += v1.x; a1.y += v1.y; a1.z += v1.z; a1.w += v1.w;
    }
    float* gs = g_gmsum + (size_t)cur * HD;
    asm volatile("red.global.add.v4.f32 [%0], {%1,%2,%3,%4};"
                 :: "l"(gs + lane * 4), "f"(a0.x), "f"(a0.y), "f"(a0.z), "f"(a0.w) : "memory");
    asm volatile("red.global.add.v4.f32 [%0], {%1,%2,%3,%4};"
                 :: "l"(gs + 128 + lane * 4), "f"(a1.x), "f"(a1.y), "f"(a1.z), "f"(a1.w) : "memory");
}

// ---------------- fused gm + head: one block per graph ----------------
__global__ __launch_bounds__(256)
void k_head(const float* __restrict__ gh, const float* __restrict__ Wlin,
            const float* __restrict__ blin, float* __restrict__ out) {
    __shared__ float gm[HD];
    int g = blockIdx.x;
    int t = threadIdx.x;
    float cnt = (float)max(g_cnt[g], 1);
    float v = g_gmsum[g * HD + t] / cnt + gh[g * HD + t];
    gm[t] = v;
    out[NG * NC + g * HD + t] = v;
    __syncthreads();
    if (t < NC) {
        float s = blin[t];
#pragma unroll 8
        for (int k = 0; k < HD; k++) s = fmaf(gm[k], Wlin[k * NC + t], s);
        out[g * NC + t] = s;
    }
}

// ---------------- launch ----------------
extern "C" void kernel_launch(void* const* d_in, const int* in_sizes, int n_in,
                              void* d_out, int out_size) {
    const float* x     = (const float*)d_in[0];
    const int*   ei    = (const int*)d_in[1];
    const int*   src   = ei;
    const int*   dst   = ei + NE;
    const int*   batch = (const int*)d_in[2];
    const float* gh    = (const float*)d_in[3];
    const float* W0    = (const float*)d_in[4];
    const float* b0    = (const float*)d_in[5];
    const float* Ws    = (const float*)d_in[6];
    const float* bs    = (const float*)d_in[7];
    const float* Wlin  = (const float*)d_in[8];
    const float* blin  = (const float*)d_in[9];
    float* out = (float*)d_out;

    dim3 ggrid((NN + 127) / 128, HD / 128);
    const int propBlocks  = (NN + 3) / 4;
    const int propxBlocks = (NN + 7) / 8;
    const int nsb = (NN + SCAN_B - 1) / SCAN_B;
    const int splitTotal = FD * HD + NL * HD * HD;

    k_init<<<(NN + 255) / 256, 256>>>();
    k_count<<<(NE + 255) / 256, 256>>>(dst, batch);
    k_scan1<<<nsb, SCAN_B>>>();
    k_bsplit<<<(splitTotal + 255) / 256, 256>>>(W0, Ws);
    k_scan2p<<<1, 256>>>(nsb);
    k_scan3<<<nsb, SCAN_B>>>();
    k_scatter<<<(NE + 255) / 256, 256>>>(src, dst);
    k_rgemm<<<dim3(2, NL), 256>>>(gh, Ws);

    // layer 0: z = P x (narrow) ; h0 = z @ W0 + b0
    k_prop_x<<<propxBlocks, 256>>>(x);
    k_gemm<FD, -1><<<ggrid, 256>>>(nullptr, b0);

    // hidden layers: t = h @ Ws[l] + R_l[batch] ; h = relu(P t + bs[l])
    k_gemm<HD, 0><<<ggrid, 256>>>(batch, nullptr);
    k_prop<<<propBlocks, 256>>>(bs + 0 * HD);
    k_gemm<HD, 1><<<ggrid, 256>>>(batch, nullptr);
    k_prop<<<propBlocks, 256>>>(bs + 1 * HD);
    k_gemm<HD, 2><<<ggrid, 256>>>(batch, nullptr);
    k_prop<<<propBlocks, 256>>>(bs + 2 * HD);

    const int poolWarps = (NN + POOL_NPW - 1) / POOL_NPW;
    k_pool_accum<<<(poolWarps * 32 + 255) / 256, 256>>>(batch);
    k_head<<<NG, 256>>>(gh, Wlin, blin, out);
}

// round 14
// speedup vs baseline: 1.2843x; 1.1664x over previous
#include <cuda_runtime.h>
#include <cstdint>

static const int NN = 50000;
static const int NE = 800000;
static const int FD = 128;
static const int HD = 256;
static const int NG = 128;
static const int NC = 10;
static const int NL = 3;

// pre-split packed-bf16 weights: W0 (64 kpairs x 256) + 3x Ws (128 kpairs x 256)
static const int BS_W0   = (FD / 2) * HD;            // 16384
static const int BS_WL   = (HD / 2) * HD;            // 32768
static const int BS_TOT  = BS_W0 + NL * BS_WL;       // 114688

// Scratch
__device__ float g_h[(long long)NN * HD];
__device__ float g_z[(long long)NN * HD];
__device__ float g_inv[NN];
__device__ int   g_deg[NN];
__device__ int   g_rowptr[NN + 1];
__device__ int   g_pos[NN];
__device__ int   g_csrc[NE];
__device__ int   g_bsum[256];
__device__ int   g_boff[256];
__device__ float g_R[NL * NG * HD];
__device__ uint2 g_Bsplit[BS_TOT];     // (hi_pack, lo_pack) bf16x2 per (kpair, n)
__device__ float g_gmsum[NG * HD];
__device__ int   g_cnt[NG];

// ---------------- init ----------------
__global__ void k_init() {
    int i = blockIdx.x * blockDim.x + threadIdx.x;
    if (i < NN) g_deg[i] = 0;
    if (i < NG * HD) g_gmsum[i] = 0.f;
    if (i < NG) g_cnt[i] = 0;
}
__global__ void k_count(const int* __restrict__ dst, const int* __restrict__ batch) {
    int e = blockIdx.x * blockDim.x + threadIdx.x;
    if (e < NE) atomicAdd(&g_deg[dst[e]], 1);
    if (e < NN) atomicAdd(&g_cnt[batch[e]], 1);
}

// ---------------- BF16 split helpers ----------------
// pack(x,y): lower16 = bf16(x) (even k), upper16 = bf16(y) (odd k)
__device__ __forceinline__ unsigned bf_split2(float x, float y, unsigned& lo) {
    unsigned hi;
    asm("cvt.rn.bf16x2.f32 %0, %1, %2;" : "=r"(hi) : "f"(y), "f"(x));
    float hx = __uint_as_float(hi << 16);
    float hy = __uint_as_float(hi & 0xFFFF0000u);
    asm("cvt.rn.bf16x2.f32 %0, %1, %2;" : "=r"(lo) : "f"(y - hy), "f"(x - hx));
    return hi;
}
__device__ __forceinline__ void mma_bf16(float4& c, const unsigned a[4], const unsigned b[2]) {
    asm volatile(
        "mma.sync.aligned.m16n8k16.row.col.f32.bf16.bf16.f32 "
        "{%0,%1,%2,%3}, {%4,%5,%6,%7}, {%8,%9}, {%0,%1,%2,%3};"
        : "+f"(c.x), "+f"(c.y), "+f"(c.z), "+f"(c.w)
        : "r"(a[0]), "r"(a[1]), "r"(a[2]), "r"(a[3]), "r"(b[0]), "r"(b[1]));
}

// ---------------- weight pre-split (packed bf16 pairs) ----------------
__global__ void k_bsplit(const float* __restrict__ W0, const float* __restrict__ Ws) {
    int i = blockIdx.x * blockDim.x + threadIdx.x;
    if (i >= BS_TOT) return;
    const float* W;
    int p, n;
    if (i < BS_W0) {
        W = W0; p = i / HD; n = i % HD;
    } else {
        int j = i - BS_W0;
        int l = j / BS_WL;
        int r = j % BS_WL;
        W = Ws + (size_t)l * HD * HD;
        p = r / HD; n = r % HD;
    }
    float v0 = W[(size_t)(2 * p) * HD + n];
    float v1 = W[(size_t)(2 * p + 1) * HD + n];
    unsigned lo;
    unsigned hi = bf_split2(v0, v1, lo);
    g_Bsplit[i] = make_uint2(hi, lo);
}

// ---------------- CSR build ----------------
#define SCAN_B 256
__global__ void k_scan1() {
    __shared__ int sh[SCAN_B];
    int i = blockIdx.x * SCAN_B + threadIdx.x;
    int v = (i < NN) ? g_deg[i] : 0;
    sh[threadIdx.x] = v;
    __syncthreads();
    for (int s = SCAN_B / 2; s > 0; s >>= 1) {
        if (threadIdx.x < s) sh[threadIdx.x] += sh[threadIdx.x + s];
        __syncthreads();
    }
    if (threadIdx.x == 0) g_bsum[blockIdx.x] = sh[0];
}
__global__ void k_scan2p(int nblocks) {
    __shared__ int sh[256];
    int t = threadIdx.x;
    int v = (t < nblocks) ? g_bsum[t] : 0;
    sh[t] = v;
    __syncthreads();
    for (int s = 1; s < 256; s <<= 1) {
        int u = (t >= s) ? sh[t - s] : 0;
        __syncthreads();
        sh[t] += u;
        __syncthreads();
    }
    if (t < nblocks) g_boff[t] = sh[t] - v;
    if (t == 255) g_rowptr[NN] = sh[255];
}
__global__ void k_scan3() {
    __shared__ int sh[SCAN_B];
    int i = blockIdx.x * SCAN_B + threadIdx.x;
    int v = (i < NN) ? g_deg[i] : 0;
    sh[threadIdx.x] = v;
    __syncthreads();
    for (int s = 1; s < SCAN_B; s <<= 1) {
        int t = (threadIdx.x >= s) ? sh[threadIdx.x - s] : 0;
        __syncthreads();
        sh[threadIdx.x] += t;
        __syncthreads();
    }
    if (i < NN) {
        int excl = g_boff[blockIdx.x] + sh[threadIdx.x] - v;
        g_rowptr[i] = excl;
        g_pos[i] = excl;
        g_inv[i] = rsqrtf((float)(v + 1));
    }
}
__global__ void k_scatter(const int* __restrict__ src, const int* __restrict__ dst) {
    int e = blockIdx.x * blockDim.x + threadIdx.x;
    if (e >= NE) return;
    int d = dst[e];
    int slot = atomicAdd(&g_pos[d], 1);
    g_csrc[slot] = src[e];
}

// ---------------- small GEMM: g_R[l] = gh @ Ws[l] (fp32, exact) ----------------
__global__ __launch_bounds__(256)
void k_rgemm(const float* __restrict__ gh, const float* __restrict__ Ws) {
    __shared__ float Ag[128 * 36];
    __shared__ float Bg[32 * 132];
    const float* B = Ws + (size_t)blockIdx.y * HD * HD;
    const int colBase = blockIdx.x * 128;
    const int tid = threadIdx.x;
    const int tx = tid & 15, ty = tid >> 4;
    float acc[8][8];
#pragma unroll
    for (int i = 0; i < 8; i++)
#pragma unroll
        for (int j = 0; j < 8; j++) acc[i][j] = 0.f;

    const int ar = tid >> 1, ak = (tid & 1) * 16;
    const int br = tid >> 3, bc = (tid & 7) * 16;
    for (int kt = 0; kt < HD; kt += 32) {
#pragma unroll
        for (int q = 0; q < 4; q++) {
            float4 v = *(const float4*)(gh + (size_t)ar * HD + kt + ak + 4 * q);
            *(float4*)&Ag[ar * 36 + ak + 4 * q] = v;
            float4 w = *(const float4*)(B + (size_t)(kt + br) * HD + colBase + bc + 4 * q);
            *(float4*)&Bg[br * 132 + bc + 4 * q] = w;
        }
        __syncthreads();
#pragma unroll
        for (int kk = 0; kk < 32; kk++) {
            float a[8], b[8];
#pragma unroll
            for (int i = 0; i < 8; i++) a[i] = Ag[(ty * 8 + i) * 36 + kk];
            *(float4*)(b)     = *(const float4*)&Bg[kk * 132 + tx * 8];
            *(float4*)(b + 4) = *(const float4*)&Bg[kk * 132 + tx * 8 + 4];
#pragma unroll
            for (int i = 0; i < 8; i++)
#pragma unroll
                for (int j = 0; j < 8; j++) acc[i][j] = fmaf(a[i], b[j], acc[i][j]);
        }
        __syncthreads();
    }
    float* outp = g_R + (size_t)blockIdx.y * NG * HD;
#pragma unroll
    for (int i = 0; i < 8; i++)
#pragma unroll
        for (int j = 0; j < 2; j++)
            *(float4*)(outp + (size_t)(ty * 8 + i) * HD + colBase + tx * 8 + 4 * j) =
                make_float4(acc[i][4 * j], acc[i][4 * j + 1], acc[i][4 * j + 2], acc[i][4 * j + 3]);
}

// ---------------- main tensor GEMM: split-BF16 m16n8k16, 3-term ----------------
// LIDX < 0: A = g_z (N x KD), out = g_h, epilogue += bias[col], B = W0 split
// LIDX >= 0: A = g_h (N x 256), out = g_z, epilogue += g_R[LIDX][batch[row]], B = Ws[LIDX] split
#define AS2_W 20   // uint2 stride per A row (16 kpairs + 4 pad); 40 u32 == 8 mod 32
#define BS2_W 132  // uint2 stride per B kpair row (128 + 4 pad); 264 u32 == 8 mod 32
template<int KD, int LIDX>
__global__ __launch_bounds__(256, 2)
void k_gemm(const int* __restrict__ batch, const float* __restrict__ bias) {
    __shared__ uint2 As2[128 * AS2_W];  // 20.0 KB
    __shared__ uint2 Bs2[16 * BS2_W];   // 16.5 KB
    const int tid  = threadIdx.x;
    const int lane = tid & 31;
    const int warp = tid >> 5;
    const int wm = warp >> 1;
    const int wn = warp & 1;
    const int rowBase = blockIdx.x * 128;
    const int colBase = blockIdx.y * 128;

    const int arow = tid >> 1;          // A stage: row 0..127
    const int akh  = tid & 1;           // which 16-k half
    const int bk   = tid >> 4;          // B stage: kpair row 0..15
    const int bc8  = (tid & 15) * 8;    // 8 uint2 per thread

    const int aRowG = rowBase + arow;
    const bool rowOK = (aRowG < NN);
    const float* aPtr = (LIDX < 0 ? (const float*)g_z : (const float*)g_h) + (size_t)aRowG * KD;
    float* outBase = (LIDX < 0 ? g_h : g_z);
    const uint2* B2 = g_Bsplit + (LIDX < 0 ? 0 : BS_W0 + (size_t)LIDX * BS_WL);

    float4 acc[2][8];
#pragma unroll
    for (int i = 0; i < 2; i++)
#pragma unroll
        for (int j = 0; j < 8; j++) acc[i][j] = make_float4(0.f, 0.f, 0.f, 0.f);

    for (int kt = 0; kt < KD; kt += 32) {
        // ---- stage A: load 16 fp32, split once, store packed (hi,lo) pairs ----
        {
            float av[16];
#pragma unroll
            for (int q = 0; q < 4; q++) {
                float4 v = make_float4(0.f, 0.f, 0.f, 0.f);
                if (rowOK) v = *(const float4*)(aPtr + kt + akh * 16 + 4 * q);
                av[4 * q] = v.x; av[4 * q + 1] = v.y; av[4 * q + 2] = v.z; av[4 * q + 3] = v.w;
            }
#pragma unroll
            for (int p = 0; p < 4; p++) {
                unsigned lo0, lo1;
                unsigned hi0 = bf_split2(av[4 * p],     av[4 * p + 1], lo0);
                unsigned hi1 = bf_split2(av[4 * p + 2], av[4 * p + 3], lo1);
                *(uint4*)&As2[arow * AS2_W + akh * 8 + 2 * p] = make_uint4(hi0, lo0, hi1, lo1);
            }
        }
        // ---- stage pre-split B (16 kpair rows = full k32) ----
        {
            const uint2* bg = B2 + (size_t)(kt / 2 + bk) * HD + colBase + bc8;
            uint2* bs = &Bs2[bk * BS2_W + bc8];
#pragma unroll
            for (int i = 0; i < 4; i++)
                *(uint4*)(bs + i * 2) = *(const uint4*)(bg + i * 2);
        }
        __syncthreads();

#pragma unroll
        for (int s = 0; s < 2; s++) {       // two k16 steps
            const int kp = s * 8 + (lane & 3);
            unsigned ah[2][4], al[2][4];
#pragma unroll
            for (int i = 0; i < 2; i++) {
                int r = wm * 32 + i * 16 + (lane >> 2);
                uint2 p0 = As2[r * AS2_W + kp];
                uint2 p1 = As2[(r + 8) * AS2_W + kp];
                uint2 p2 = As2[r * AS2_W + kp + 4];
                uint2 p3 = As2[(r + 8) * AS2_W + kp + 4];
                ah[i][0] = p0.x; al[i][0] = p0.y;
                ah[i][1] = p1.x; al[i][1] = p1.y;
                ah[i][2] = p2.x; al[i][2] = p2.y;
                ah[i][3] = p3.x; al[i][3] = p3.y;
            }
#pragma unroll
            for (int h = 0; h < 2; h++) {
                unsigned bh[4][2], bl[4][2];
#pragma unroll
                for (int j = 0; j < 4; j++) {
                    int col = wn * 64 + h * 32 + j * 8 + (lane >> 2);
                    uint2 q0 = Bs2[kp * BS2_W + col];
                    uint2 q1 = Bs2[(kp + 4) * BS2_W + col];
                    bh[j][0] = q0.x; bl[j][0] = q0.y;
                    bh[j][1] = q1.x; bl[j][1] = q1.y;
                }
#pragma unroll
                for (int i = 0; i < 2; i++)
#pragma unroll
                    for (int j = 0; j < 4; j++) {
                        float4& c4 = acc[i][h * 4 + j];
                        mma_bf16(c4, ah[i], bh[j]);   // hi*hi
                        mma_bf16(c4, ah[i], bl[j]);   // hi*lo
                        mma_bf16(c4, al[i], bh[j]);   // lo*hi
                    }
            }
        }
        __syncthreads();
    }

    // ---- epilogue ----
#pragma unroll
    for (int i = 0; i < 2; i++) {
        int r0 = rowBase + wm * 32 + i * 16 + (lane >> 2);
        const float* Ra = nullptr;
        const float* Rb = nullptr;
        if (LIDX >= 0) {
            if (r0 < NN)     Ra = g_R + (size_t)LIDX * NG * HD + (size_t)batch[r0] * HD;
            if (r0 + 8 < NN) Rb = g_R + (size_t)LIDX * NG * HD + (size_t)batch[r0 + 8] * HD;
        }
#pragma unroll
        for (int j = 0; j < 8; j++) {
            int c = colBase + wn * 64 + j * 8 + 2 * (lane & 3);
            float4 v = acc[i][j];
            float2 bc2 = make_float2(0.f, 0.f);
            if (LIDX < 0) bc2 = *(const float2*)(bias + c);
            if (r0 < NN) {
                float2 o = make_float2(v.x, v.y);
                if (LIDX >= 0) { float2 r = *(const float2*)(Ra + c); o.x += r.x; o.y += r.y; }
                else           { o.x += bc2.x; o.y += bc2.y; }
                *(float2*)(outBase + (size_t)r0 * HD + c) = o;
            }
            if (r0 + 8 < NN) {
                float2 o = make_float2(v.z, v.w);
                if (LIDX >= 0) { float2 r = *(const float2*)(Rb + c); o.x += r.x; o.y += r.y; }
                else           { o.x += bc2.x; o.y += bc2.y; }
                *(float2*)(outBase + (size_t)(r0 + 8) * HD + c) = o;
            }
        }
    }
}

// ---------------- propagation ----------------
__device__ __forceinline__ void acc4(float4& acc, const float4& u, float wt) {
    acc.x = fmaf(u.x, wt, acc.x);
    acc.y = fmaf(u.y, wt, acc.y);
    acc.z = fmaf(u.z, wt, acc.z);
    acc.w = fmaf(u.w, wt, acc.w);
}

// z = P x  (N x 128). One warp per node.
__global__ __launch_bounds__(256)
void k_prop_x(const float* __restrict__ x) {
    int node = blockIdx.x * 8 + (threadIdx.x >> 5);
    int lane = threadIdx.x & 31;
    if (node >= NN) return;
    int off = lane * 4;
    float invd = g_inv[node];
    float sq = invd * invd;
    float4 h0 = *(const float4*)(x + (size_t)node * FD + off);
    float4 acc = make_float4(h0.x * sq, h0.y * sq, h0.z * sq, h0.w * sq);
    int e   = g_rowptr[node];
    int end = g_rowptr[node + 1];
    for (; e + 8 <= end; e += 8) {
        int s[8];
        float wt[8];
        float4 u[8];
#pragma unroll
        for (int q = 0; q < 8; q++) s[q] = g_csrc[e + q];
#pragma unroll
        for (int q = 0; q < 8; q++) u[q] = *(const float4*)(x + (size_t)s[q] * FD + off);
#pragma unroll
        for (int q = 0; q < 8; q++) wt[q] = g_inv[s[q]] * invd;
#pragma unroll
        for (int q = 0; q < 8; q++) acc4(acc, u[q], wt[q]);
    }
    for (; e < end; e++) {
        int s0 = g_csrc[e];
        float w0 = g_inv[s0] * invd;
        float4 u0 = *(const float4*)(x + (size_t)s0 * FD + off);
        acc4(acc, u0, w0);
    }
    *(float4*)(g_z + (size_t)node * FD + off) = acc;
}

// h = relu(P t + bias), t in g_z (N x 256), out g_h. 2 warps per node.
__global__ __launch_bounds__(256)
void k_prop(const float* __restrict__ bias) {
    int node = blockIdx.x * 4 + (threadIdx.x >> 6);
    int half = (threadIdx.x >> 5) & 1;
    int lane = threadIdx.x & 31;
    if (node >= NN) return;
    int off = half * 128 + lane * 4;
    float invd = g_inv[node];
    float sq = invd * invd;
    float4 h0 = *(const float4*)(g_z + (size_t)node * HD + off);
    float4 b0 = *(const float4*)(bias + off);
    float4 acc = make_float4(fmaf(h0.x, sq, b0.x), fmaf(h0.y, sq, b0.y),
                             fmaf(h0.z, sq, b0.z), fmaf(h0.w, sq, b0.w));
    int e   = g_rowptr[node];
    int end = g_rowptr[node + 1];
    for (; e + 8 <= end; e += 8) {
        int s[8];
        float wt[8];
        float4 u[8];
#pragma unroll
        for (int q = 0; q < 8; q++) s[q] = g_csrc[e + q];
#pragma unroll
        for (int q = 0; q < 8; q++) u[q] = *(const float4*)(g_z + (size_t)s[q] * HD + off);
#pragma unroll
        for (int q = 0; q < 8; q++) wt[q] = g_inv[s[q]] * invd;
#pragma unroll
        for (int q = 0; q < 8; q++) acc4(acc, u[q], wt[q]);
    }
    for (; e + 2 <= end; e += 2) {
        int s0 = g_csrc[e], s1 = g_csrc[e + 1];
        float4 u0 = *(const float4*)(g_z + (size_t)s0 * HD + off);
        float4 u1 = *(const float4*)(g_z + (size_t)s1 * HD + off);
        float w0 = g_inv[s0] * invd, w1 = g_inv[s1] * invd;
        acc4(acc, u0, w0);
        acc4(acc, u1, w1);
    }
    if (e < end) {
        int s0 = g_csrc[e];
        float w0 = g_inv[s0] * invd;
        float4 u0 = *(const float4*)(g_z + (size_t)s0 * HD + off);
        acc4(acc, u0, w0);
    }
    acc.x = fmaxf(acc.x, 0.f); acc.y = fmaxf(acc.y, 0.f);
    acc.z = fmaxf(acc.z, 0.f); acc.w = fmaxf(acc.w, 0.f);
    *(float4*)(g_h + (size_t)node * HD + off) = acc;
}

// ---------------- pooling (reads g_h) ----------------
#define POOL_NPW 8
__global__ void k_pool_accum(const int* __restrict__ batch) {
    int w = (blockIdx.x * blockDim.x + threadIdx.x) >> 5;
    int lane = threadIdx.x & 31;
    int n0 = w * POOL_NPW;
    if (n0 >= NN) return;
    int nend = n0 + POOL_NPW;
    if (nend > NN) nend = NN;
    float4 a0 = make_float4(0.f, 0.f, 0.f, 0.f);
    float4 a1 = a0;
    int cur = batch[n0];
    for (int n = n0; n < nend; n++) {
        int b = batch[n];
        if (b != cur) {
            float* gs = g_gmsum + (size_t)cur * HD;
            asm volatile("red.global.add.v4.f32 [%0], {%1,%2,%3,%4};"
                         :: "l"(gs + lane * 4), "f"(a0.x), "f"(a0.y), "f"(a0.z), "f"(a0.w) : "memory");
            asm volatile("red.global.add.v4.f32 [%0], {%1,%2,%3,%4};"
                         :: "l"(gs + 128 + lane * 4), "f"(a1.x), "f"(a1.y), "f"(a1.z), "f"(a1.w) : "memory");
            a0 = make_float4(0.f, 0.f, 0.f, 0.f);
            a1 = a0;
            cur = b;
        }
        float4 v0 = *(const float4*)(g_h + (size_t)n * HD + lane * 4);
        float4 v1 = *(const float4*)(g_h + (size_t)n * HD + 128 + lane * 4);
        a0.x += v0.x; a0.y += v0.y; a0.z += v0.z; a0.w += v0.w;
        a1.x += v1.x; a1.y += v1.y; a1.z += v1.z; a1.w += v1.w;
    }
    float* gs = g_gmsum + (size_t)cur * HD;
    asm volatile("red.global.add.v4.f32 [%0], {%1,%2,%3,%4};"
                 :: "l"(gs + lane * 4), "f"(a0.x), "f"(a0.y), "f"(a0.z), "f"(a0.w) : "memory");
    asm volatile("red.global.add.v4.f32 [%0], {%1,%2,%3,%4};"
                 :: "l"(gs + 128 + lane * 4), "f"(a1.x), "f"(a1.y), "f"(a1.z), "f"(a1.w) : "memory");
}

// ---------------- fused gm + head ----------------
__global__ __launch_bounds__(256)
void k_head(const float* __restrict__ gh, const float* __restrict__ Wlin,
            const float* __restrict__ blin, float* __restrict__ out) {
    __shared__ float gm[HD];
    int g = blockIdx.x;
    int t = threadIdx.x;
    float cnt = (float)max(g_cnt[g], 1);
    float v = g_gmsum[g * HD + t] / cnt + gh[g * HD + t];
    gm[t] = v;
    out[NG * NC + g * HD + t] = v;
    __syncthreads();
    if (t < NC) {
        float s = blin[t];
#pragma unroll 8
        for (int k = 0; k < HD; k++) s = fmaf(gm[k], Wlin[k * NC + t], s);
        out[g * NC + t] = s;
    }
}

// ---------------- launch ----------------
extern "C" void kernel_launch(void* const* d_in, const int* in_sizes, int n_in,
                              void* d_out, int out_size) {
    const float* x     = (const float*)d_in[0];
    const int*   ei    = (const int*)d_in[1];
    const int*   src   = ei;
    const int*   dst   = ei + NE;
    const int*   batch = (const int*)d_in[2];
    const float* gh    = (const float*)d_in[3];
    const float* W0    = (const float*)d_in[4];
    const float* b0    = (const float*)d_in[5];
    const float* Ws    = (const float*)d_in[6];
    const float* bs    = (const float*)d_in[7];
    const float* Wlin  = (const float*)d_in[8];
    const float* blin  = (const float*)d_in[9];
    float* out = (float*)d_out;

    dim3 ggrid((NN + 127) / 128, HD / 128);
    const int propBlocks  = (NN + 3) / 4;
    const int propxBlocks = (NN + 7) / 8;
    const int nsb = (NN + SCAN_B - 1) / SCAN_B;

    k_init<<<(NN + 255) / 256, 256>>>();
    k_count<<<(NE + 255) / 256, 256>>>(dst, batch);
    k_scan1<<<nsb, SCAN_B>>>();
    k_bsplit<<<(BS_TOT + 255) / 256, 256>>>(W0, Ws);
    k_scan2p<<<1, 256>>>(nsb);
    k_scan3<<<nsb, SCAN_B>>>();
    k_scatter<<<(NE + 255) / 256, 256>>>(src, dst);
    k_rgemm<<<dim3(2, NL), 256>>>(gh, Ws);

    // layer 0: z = P x (narrow) ; h0 = z @ W0 + b0
    k_prop_x<<<propxBlocks, 256>>>(x);
    k_gemm<FD, -1><<<ggrid, 256>>>(nullptr, b0);

    // hidden layers: t = h @ Ws[l] + R_l[batch] ; h = relu(P t + bs[l])
    k_gemm<HD, 0><<<ggrid, 256>>>(batch, nullptr);
    k_prop<<<propBlocks, 256>>>(bs + 0 * HD);
    k_gemm<HD, 1><<<ggrid, 256>>>(batch, nullptr);
    k_prop<<<propBlocks, 256>>>(bs + 1 * HD);
    k_gemm<HD, 2><<<ggrid, 256>>>(batch, nullptr);
    k_prop<<<propBlocks, 256>>>(bs + 2 * HD);

    const int poolWarps = (NN + POOL_NPW - 1) / POOL_NPW;
    k_pool_accum<<<(poolWarps * 32 + 255) / 256, 256>>>(batch);
    k_head<<<NG, 256>>>(gh, Wlin, blin, out);
}

// round 16
// speedup vs baseline: 1.2867x; 1.0018x over previous
#include <cuda_runtime.h>
#include <cstdint>

static const int NN = 50000;
static const int NE = 800000;
static const int FD = 128;
static const int HD = 256;
static const int NG = 128;
static const int NC = 10;
static const int NL = 3;

// pre-split packed-bf16 weights: W0 (64 kpairs x 256) + 3x Ws (128 kpairs x 256)
static const int BS_W0   = (FD / 2) * HD;            // 16384
static const int BS_WL   = (HD / 2) * HD;            // 32768
static const int BS_TOT  = BS_W0 + NL * BS_WL;       // 114688

// Scratch
__device__ float g_h[(long long)NN * HD];
__device__ float g_z[(long long)NN * HD];
__device__ float g_inv[NN];
__device__ int   g_deg[NN];
__device__ int   g_rowptr[NN + 1];
__device__ int   g_pos[NN];
__device__ int   g_csrc[NE];
__device__ int   g_bsum[256];
__device__ int   g_boff[256];
__device__ float g_R[NL * NG * HD];
__device__ uint2 g_Bsplit[BS_TOT];     // (hi_pack, lo_pack) bf16x2 per (kpair, n)
__device__ float g_gmsum[NG * HD];
__device__ int   g_cnt[NG];

// ---------------- init ----------------
__global__ void k_init() {
    int i = blockIdx.x * blockDim.x + threadIdx.x;
    if (i < NN) g_deg[i] = 0;
    if (i < NG * HD) g_gmsum[i] = 0.f;
    if (i < NG) g_cnt[i] = 0;
}
__global__ void k_count(const int* __restrict__ dst, const int* __restrict__ batch) {
    int e = blockIdx.x * blockDim.x + threadIdx.x;
    if (e < NE) atomicAdd(&g_deg[dst[e]], 1);
    if (e < NN) atomicAdd(&g_cnt[batch[e]], 1);
}

// ---------------- BF16 split helpers ----------------
__device__ __forceinline__ unsigned bf_split2(float x, float y, unsigned& lo) {
    unsigned hi;
    asm("cvt.rn.bf16x2.f32 %0, %1, %2;" : "=r"(hi) : "f"(y), "f"(x));
    float hx = __uint_as_float(hi << 16);
    float hy = __uint_as_float(hi & 0xFFFF0000u);
    asm("cvt.rn.bf16x2.f32 %0, %1, %2;" : "=r"(lo) : "f"(y - hy), "f"(x - hx));
    return hi;
}
__device__ __forceinline__ void mma_bf16(float4& c, const unsigned a[4], const unsigned b[2]) {
    asm volatile(
        "mma.sync.aligned.m16n8k16.row.col.f32.bf16.bf16.f32 "
        "{%0,%1,%2,%3}, {%4,%5,%6,%7}, {%8,%9}, {%0,%1,%2,%3};"
        : "+f"(c.x), "+f"(c.y), "+f"(c.z), "+f"(c.w)
        : "r"(a[0]), "r"(a[1]), "r"(a[2]), "r"(a[3]), "r"(b[0]), "r"(b[1]));
}

// ---------------- weight pre-split (packed bf16 pairs) ----------------
__global__ void k_bsplit(const float* __restrict__ W0, const float* __restrict__ Ws) {
    int i = blockIdx.x * blockDim.x + threadIdx.x;
    if (i >= BS_TOT) return;
    const float* W;
    int p, n;
    if (i < BS_W0) {
        W = W0; p = i / HD; n = i % HD;
    } else {
        int j = i - BS_W0;
        int l = j / BS_WL;
        int r = j % BS_WL;
        W = Ws + (size_t)l * HD * HD;
        p = r / HD; n = r % HD;
    }
    float v0 = W[(size_t)(2 * p) * HD + n];
    float v1 = W[(size_t)(2 * p + 1) * HD + n];
    unsigned lo;
    unsigned hi = bf_split2(v0, v1, lo);
    g_Bsplit[i] = make_uint2(hi, lo);
}

// ---------------- CSR build ----------------
#define SCAN_B 256
__global__ void k_scan1() {
    __shared__ int sh[SCAN_B];
    int i = blockIdx.x * SCAN_B + threadIdx.x;
    int v = (i < NN) ? g_deg[i] : 0;
    sh[threadIdx.x] = v;
    __syncthreads();
    for (int s = SCAN_B / 2; s > 0; s >>= 1) {
        if (threadIdx.x < s) sh[threadIdx.x] += sh[threadIdx.x + s];
        __syncthreads();
    }
    if (threadIdx.x == 0) g_bsum[blockIdx.x] = sh[0];
}
__global__ void k_scan2p(int nblocks) {
    __shared__ int sh[256];
    int t = threadIdx.x;
    int v = (t < nblocks) ? g_bsum[t] : 0;
    sh[t] = v;
    __syncthreads();
    for (int s = 1; s < 256; s <<= 1) {
        int u = (t >= s) ? sh[t - s] : 0;
        __syncthreads();
        sh[t] += u;
        __syncthreads();
    }
    if (t < nblocks) g_boff[t] = sh[t] - v;
    if (t == 255) g_rowptr[NN] = sh[255];
}
__global__ void k_scan3() {
    __shared__ int sh[SCAN_B];
    int i = blockIdx.x * SCAN_B + threadIdx.x;
    int v = (i < NN) ? g_deg[i] : 0;
    sh[threadIdx.x] = v;
    __syncthreads();
    for (int s = 1; s < SCAN_B; s <<= 1) {
        int t = (threadIdx.x >= s) ? sh[threadIdx.x - s] : 0;
        __syncthreads();
        sh[threadIdx.x] += t;
        __syncthreads();
    }
    if (i < NN) {
        int excl = g_boff[blockIdx.x] + sh[threadIdx.x] - v;
        g_rowptr[i] = excl;
        g_pos[i] = excl;
        g_inv[i] = rsqrtf((float)(v + 1));
    }
}
__global__ void k_scatter(const int* __restrict__ src, const int* __restrict__ dst) {
    int e = blockIdx.x * blockDim.x + threadIdx.x;
    if (e >= NE) return;
    int d = dst[e];
    int slot = atomicAdd(&g_pos[d], 1);
    g_csrc[slot] = src[e];
}

// ---------------- small GEMM: g_R[l] = gh @ Ws[l] (fp32, exact) ----------------
__global__ __launch_bounds__(256)
void k_rgemm(const float* __restrict__ gh, const float* __restrict__ Ws) {
    __shared__ float Ag[128 * 36];
    __shared__ float Bg[32 * 132];
    const float* B = Ws + (size_t)blockIdx.y * HD * HD;
    const int colBase = blockIdx.x * 128;
    const int tid = threadIdx.x;
    const int tx = tid & 15, ty = tid >> 4;
    float acc[8][8];
#pragma unroll
    for (int i = 0; i < 8; i++)
#pragma unroll
        for (int j = 0; j < 8; j++) acc[i][j] = 0.f;

    const int ar = tid >> 1, ak = (tid & 1) * 16;
    const int br = tid >> 3, bc = (tid & 7) * 16;
    for (int kt = 0; kt < HD; kt += 32) {
#pragma unroll
        for (int q = 0; q < 4; q++) {
            float4 v = *(const float4*)(gh + (size_t)ar * HD + kt + ak + 4 * q);
            *(float4*)&Ag[ar * 36 + ak + 4 * q] = v;
            float4 w = *(const float4*)(B + (size_t)(kt + br) * HD + colBase + bc + 4 * q);
            *(float4*)&Bg[br * 132 + bc + 4 * q] = w;
        }
        __syncthreads();
#pragma unroll
        for (int kk = 0; kk < 32; kk++) {
            float a[8], b[8];
#pragma unroll
            for (int i = 0; i < 8; i++) a[i] = Ag[(ty * 8 + i) * 36 + kk];
            *(float4*)(b)     = *(const float4*)&Bg[kk * 132 + tx * 8];
            *(float4*)(b + 4) = *(const float4*)&Bg[kk * 132 + tx * 8 + 4];
#pragma unroll
            for (int i = 0; i < 8; i++)
#pragma unroll
                for (int j = 0; j < 8; j++) acc[i][j] = fmaf(a[i], b[j], acc[i][j]);
        }
        __syncthreads();
    }
    float* outp = g_R + (size_t)blockIdx.y * NG * HD;
#pragma unroll
    for (int i = 0; i < 8; i++)
#pragma unroll
        for (int j = 0; j < 2; j++)
            *(float4*)(outp + (size_t)(ty * 8 + i) * HD + colBase + tx * 8 + 4 * j) =
                make_float4(acc[i][4 * j], acc[i][4 * j + 1], acc[i][4 * j + 2], acc[i][4 * j + 3]);
}

// ---------------- main tensor GEMM: split-BF16 m16n8k16, 3-term ----------------
#define AS2_W 20
#define BS2_W 132
template<int KD, int LIDX>
__global__ __launch_bounds__(256, 2)
void k_gemm(const int* __restrict__ batch, const float* __restrict__ bias) {
    __shared__ uint2 As2[128 * AS2_W];
    __shared__ uint2 Bs2[16 * BS2_W];
    const int tid  = threadIdx.x;
    const int lane = tid & 31;
    const int warp = tid >> 5;
    const int wm = warp >> 1;
    const int wn = warp & 1;
    const int rowBase = blockIdx.x * 128;
    const int colBase = blockIdx.y * 128;

    const int arow = tid >> 1;
    const int akh  = tid & 1;
    const int bk   = tid >> 4;
    const int bc8  = (tid & 15) * 8;

    const int aRowG = rowBase + arow;
    const bool rowOK = (aRowG < NN);
    const float* aPtr = (LIDX < 0 ? (const float*)g_z : (const float*)g_h) + (size_t)aRowG * KD;
    float* outBase = (LIDX < 0 ? g_h : g_z);
    const uint2* B2 = g_Bsplit + (LIDX < 0 ? 0 : BS_W0 + (size_t)LIDX * BS_WL);

    float4 acc[2][8];
#pragma unroll
    for (int i = 0; i < 2; i++)
#pragma unroll
        for (int j = 0; j < 8; j++) acc[i][j] = make_float4(0.f, 0.f, 0.f, 0.f);

    for (int kt = 0; kt < KD; kt += 32) {
        {
            float av[16];
#pragma unroll
            for (int q = 0; q < 4; q++) {
                float4 v = make_float4(0.f, 0.f, 0.f, 0.f);
                if (rowOK) v = *(const float4*)(aPtr + kt + akh * 16 + 4 * q);
                av[4 * q] = v.x; av[4 * q + 1] = v.y; av[4 * q + 2] = v.z; av[4 * q + 3] = v.w;
            }
#pragma unroll
            for (int p = 0; p < 4; p++) {
                unsigned lo0, lo1;
                unsigned hi0 = bf_split2(av[4 * p],     av[4 * p + 1], lo0);
                unsigned hi1 = bf_split2(av[4 * p + 2], av[4 * p + 3], lo1);
                *(uint4*)&As2[arow * AS2_W + akh * 8 + 2 * p] = make_uint4(hi0, lo0, hi1, lo1);
            }
        }
        {
            const uint2* bg = B2 + (size_t)(kt / 2 + bk) * HD + colBase + bc8;
            uint2* bs = &Bs2[bk * BS2_W + bc8];
#pragma unroll
            for (int i = 0; i < 4; i++)
                *(uint4*)(bs + i * 2) = *(const uint4*)(bg + i * 2);
        }
        __syncthreads();

#pragma unroll
        for (int s = 0; s < 2; s++) {
            const int kp = s * 8 + (lane & 3);
            unsigned ah[2][4], al[2][4];
#pragma unroll
            for (int i = 0; i < 2; i++) {
                int r = wm * 32 + i * 16 + (lane >> 2);
                uint2 p0 = As2[r * AS2_W + kp];
                uint2 p1 = As2[(r + 8) * AS2_W + kp];
                uint2 p2 = As2[r * AS2_W + kp + 4];
                uint2 p3 = As2[(r + 8) * AS2_W + kp + 4];
                ah[i][0] = p0.x; al[i][0] = p0.y;
                ah[i][1] = p1.x; al[i][1] = p1.y;
                ah[i][2] = p2.x; al[i][2] = p2.y;
                ah[i][3] = p3.x; al[i][3] = p3.y;
            }
#pragma unroll
            for (int h = 0; h < 2; h++) {
                unsigned bh[4][2], bl[4][2];
#pragma unroll
                for (int j = 0; j < 4; j++) {
                    int col = wn * 64 + h * 32 + j * 8 + (lane >> 2);
                    uint2 q0 = Bs2[kp * BS2_W + col];
                    uint2 q1 = Bs2[(kp + 4) * BS2_W + col];
                    bh[j][0] = q0.x; bl[j][0] = q0.y;
                    bh[j][1] = q1.x; bl[j][1] = q1.y;
                }
#pragma unroll
                for (int i = 0; i < 2; i++)
#pragma unroll
                    for (int j = 0; j < 4; j++) {
                        float4& c4 = acc[i][h * 4 + j];
                        mma_bf16(c4, ah[i], bh[j]);
                        mma_bf16(c4, ah[i], bl[j]);
                        mma_bf16(c4, al[i], bh[j]);
                    }
            }
        }
        __syncthreads();
    }

#pragma unroll
    for (int i = 0; i < 2; i++) {
        int r0 = rowBase + wm * 32 + i * 16 + (lane >> 2);
        const float* Ra = nullptr;
        const float* Rb = nullptr;
        if (LIDX >= 0) {
            if (r0 < NN)     Ra = g_R + (size_t)LIDX * NG * HD + (size_t)batch[r0] * HD;
            if (r0 + 8 < NN) Rb = g_R + (size_t)LIDX * NG * HD + (size_t)batch[r0 + 8] * HD;
        }
#pragma unroll
        for (int j = 0; j < 8; j++) {
            int c = colBase + wn * 64 + j * 8 + 2 * (lane & 3);
            float4 v = acc[i][j];
            float2 bc2 = make_float2(0.f, 0.f);
            if (LIDX < 0) bc2 = *(const float2*)(bias + c);
            if (r0 < NN) {
                float2 o = make_float2(v.x, v.y);
                if (LIDX >= 0) { float2 r = *(const float2*)(Ra + c); o.x += r.x; o.y += r.y; }
                else           { o.x += bc2.x; o.y += bc2.y; }
                *(float2*)(outBase + (size_t)r0 * HD + c) = o;
            }
            if (r0 + 8 < NN) {
                float2 o = make_float2(v.z, v.w);
                if (LIDX >= 0) { float2 r = *(const float2*)(Rb + c); o.x += r.x; o.y += r.y; }
                else           { o.x += bc2.x; o.y += bc2.y; }
                *(float2*)(outBase + (size_t)(r0 + 8) * HD + c) = o;
            }
        }
    }
}

// ---------------- propagation ----------------
__device__ __forceinline__ void acc4(float4& acc, const float4& u, float wt) {
    acc.x = fmaf(u.x, wt, acc.x);
    acc.y = fmaf(u.y, wt, acc.y);
    acc.z = fmaf(u.z, wt, acc.z);
    acc.w = fmaf(u.w, wt, acc.w);
}

// z = P x  (N x 128). One warp per node.
__global__ __launch_bounds__(256)
void k_prop_x(const float* __restrict__ x) {
    int node = blockIdx.x * 8 + (threadIdx.x >> 5);
    int lane = threadIdx.x & 31;
    if (node >= NN) return;
    int off = lane * 4;
    float invd = g_inv[node];
    float sq = invd * invd;
    float4 h0 = *(const float4*)(x + (size_t)node * FD + off);
    float4 acc = make_float4(h0.x * sq, h0.y * sq, h0.z * sq, h0.w * sq);
    int e   = g_rowptr[node];
    int end = g_rowptr[node + 1];
    for (; e + 8 <= end; e += 8) {
        int s[8];
        float wt[8];
        float4 u[8];
#pragma unroll
        for (int q = 0; q < 8; q++) s[q] = g_csrc[e + q];
#pragma unroll
        for (int q = 0; q < 8; q++) u[q] = *(const float4*)(x + (size_t)s[q] * FD + off);
#pragma unroll
        for (int q = 0; q < 8; q++) wt[q] = g_inv[s[q]] * invd;
#pragma unroll
        for (int q = 0; q < 8; q++) acc4(acc, u[q], wt[q]);
    }
    for (; e < end; e++) {
        int s0 = g_csrc[e];
        float w0 = g_inv[s0] * invd;
        float4 u0 = *(const float4*)(x + (size_t)s0 * FD + off);
        acc4(acc, u0, w0);
    }
    *(float4*)(g_z + (size_t)node * FD + off) = acc;
}

// h = relu(P t + bias); POOL=false: write g_h; POOL=true: reduce into g_gmsum[batch].
template<bool POOL>
__global__ __launch_bounds__(256)
void k_prop(const float* __restrict__ bias, const int* __restrict__ batch) {
    int node = blockIdx.x * 4 + (threadIdx.x >> 6);
    int half = (threadIdx.x >> 5) & 1;
    int lane = threadIdx.x & 31;
    if (node >= NN) return;
    int off = half * 128 + lane * 4;
    float invd = g_inv[node];
    float sq = invd * invd;
    float4 h0 = *(const float4*)(g_z + (size_t)node * HD + off);
    float4 b0 = *(const float4*)(bias + off);
    float4 acc = make_float4(fmaf(h0.x, sq, b0.x), fmaf(h0.y, sq, b0.y),
                             fmaf(h0.z, sq, b0.z), fmaf(h0.w, sq, b0.w));
    int e   = g_rowptr[node];
    int end = g_rowptr[node + 1];
    for (; e + 8 <= end; e += 8) {
        int s[8];
        float wt[8];
        float4 u[8];
#pragma unroll
        for (int q = 0; q < 8; q++) s[q] = g_csrc[e + q];
#pragma unroll
        for (int q = 0; q < 8; q++) u[q] = *(const float4*)(g_z + (size_t)s[q] * HD + off);
#pragma unroll
        for (int q = 0; q < 8; q++) wt[q] = g_inv[s[q]] * invd;
#pragma unroll
        for (int q = 0; q < 8; q++) acc4(acc, u[q], wt[q]);
    }
    for (; e + 2 <= end; e += 2) {
        int s0 = g_csrc[e], s1 = g_csrc[e + 1];
        float4 u0 = *(const float4*)(g_z + (size_t)s0 * HD + off);
        float4 u1 = *(const float4*)(g_z + (size_t)s1 * HD + off);
        float w0 = g_inv[s0] * invd, w1 = g_inv[s1] * invd;
        acc4(acc, u0, w0);
        acc4(acc, u1, w1);
    }
    if (e < end) {
        int s0 = g_csrc[e];
        float w0 = g_inv[s0] * invd;
        float4 u0 = *(const float4*)(g_z + (size_t)s0 * HD + off);
        acc4(acc, u0, w0);
    }
    acc.x = fmaxf(acc.x, 0.f); acc.y = fmaxf(acc.y, 0.f);
    acc.z = fmaxf(acc.z, 0.f); acc.w = fmaxf(acc.w, 0.f);
    if (POOL) {
        float* gs = g_gmsum + (size_t)batch[node] * HD + off;
        asm volatile("red.global.add.v4.f32 [%0], {%1,%2,%3,%4};"
                     :: "l"(gs), "f"(acc.x), "f"(acc.y), "f"(acc.z), "f"(acc.w) : "memory");
    } else {
        *(float4*)(g_h + (size_t)node * HD + off) = acc;
    }
}

// ---------------- fused gm + head ----------------
__global__ __launch_bounds__(256)
void k_head(const float* __restrict__ gh, const float* __restrict__ Wlin,
            const float* __restrict__ blin, float* __restrict__ out) {
    __shared__ float gm[HD];
    int g = blockIdx.x;
    int t = threadIdx.x;
    float cnt = (float)max(g_cnt[g], 1);
    float v = g_gmsum[g * HD + t] / cnt + gh[g * HD + t];
    gm[t] = v;
    out[NG * NC + g * HD + t] = v;
    __syncthreads();
    if (t < NC) {
        float s = blin[t];
#pragma unroll 8
        for (int k = 0; k < HD; k++) s = fmaf(gm[k], Wlin[k * NC + t], s);
        out[g * NC + t] = s;
    }
}

// ---------------- launch ----------------
extern "C" void kernel_launch(void* const* d_in, const int* in_sizes, int n_in,
                              void* d_out, int out_size) {
    const float* x     = (const float*)d_in[0];
    const int*   ei    = (const int*)d_in[1];
    const int*   src   = ei;
    const int*   dst   = ei + NE;
    const int*   batch = (const int*)d_in[2];
    const float* gh    = (const float*)d_in[3];
    const float* W0    = (const float*)d_in[4];
    const float* b0    = (const float*)d_in[5];
    const float* Ws    = (const float*)d_in[6];
    const float* bs    = (const float*)d_in[7];
    const float* Wlin  = (const float*)d_in[8];
    const float* blin  = (const float*)d_in[9];
    float* out = (float*)d_out;

    dim3 ggrid((NN + 127) / 128, HD / 128);
    const int propBlocks  = (NN + 3) / 4;
    const int propxBlocks = (NN + 7) / 8;
    const int nsb = (NN + SCAN_B - 1) / SCAN_B;

    k_init<<<(NN + 255) / 256, 256>>>();
    k_count<<<(NE + 255) / 256, 256>>>(dst, batch);
    k_scan1<<<nsb, SCAN_B>>>();
    k_bsplit<<<(BS_TOT + 255) / 256, 256>>>(W0, Ws);
    k_scan2p<<<1, 256>>>(nsb);
    k_scan3<<<nsb, SCAN_B>>>();
    k_scatter<<<(NE + 255) / 256, 256>>>(src, dst);
    k_rgemm<<<dim3(2, NL), 256>>>(gh, Ws);

    // layer 0: z = P x (narrow) ; h0 = z @ W0 + b0
    k_prop_x<<<propxBlocks, 256>>>(x);
    k_gemm<FD, -1><<<ggrid, 256>>>(nullptr, b0);

    // hidden layers: t = h @ Ws[l] + R_l[batch] ; h = relu(P t + bs[l])
    k_gemm<HD, 0><<<ggrid, 256>>>(batch, nullptr);
    k_prop<false><<<propBlocks, 256>>>(bs + 0 * HD, nullptr);
    k_gemm<HD, 1><<<ggrid, 256>>>(batch, nullptr);
    k_prop<false><<<propBlocks, 256>>>(bs + 1 * HD, nullptr);
    k_gemm<HD, 2><<<ggrid, 256>>>(batch, nullptr);
    k_prop<true><<<propBlocks, 256>>>(bs + 2 * HD, batch);   // pool fused

    k_head<<<NG, 256>>>(gh, Wlin, blin, out);
}

// round 17
// speedup vs baseline: 1.3756x; 1.0691x over previous
#include <cuda_runtime.h>
#include <cuda_fp16.h>
#include <cstdint>

static const int NN = 50000;
static const int NE = 800000;
static const int FD = 128;
static const int HD = 256;
static const int NG = 128;
static const int NC = 10;
static const int NL = 3;

// pre-split packed-bf16 weights
static const int BS_W0   = (FD / 2) * HD;
static const int BS_WL   = (HD / 2) * HD;
static const int BS_TOT  = BS_W0 + NL * BS_WL;

// Scratch
__device__ float g_h[(long long)NN * HD];
__device__ float g_z[(long long)NN * HD];
__device__ __half g_t16[(long long)NN * HD];   // fp16 messages for propagation
__device__ float g_inv[NN];
__device__ int   g_deg[NN];
__device__ int   g_rowptr[NN + 1];
__device__ int   g_pos[NN];
__device__ int   g_csrc[NE];
__device__ int   g_bsum[256];
__device__ int   g_boff[256];
__device__ float g_R[NL * NG * HD];
__device__ uint2 g_Bsplit[BS_TOT];
__device__ float g_gmsum[NG * HD];
__device__ int   g_cnt[NG];

// ---------------- init ----------------
__global__ void k_init() {
    int i = blockIdx.x * blockDim.x + threadIdx.x;
    if (i < NN) g_deg[i] = 0;
    if (i < NG * HD) g_gmsum[i] = 0.f;
    if (i < NG) g_cnt[i] = 0;
}
__global__ void k_count(const int* __restrict__ dst, const int* __restrict__ batch) {
    int e = blockIdx.x * blockDim.x + threadIdx.x;
    if (e < NE) atomicAdd(&g_deg[dst[e]], 1);
    if (e < NN) atomicAdd(&g_cnt[batch[e]], 1);
}

// ---------------- BF16 split helpers ----------------
__device__ __forceinline__ unsigned bf_split2(float x, float y, unsigned& lo) {
    unsigned hi;
    asm("cvt.rn.bf16x2.f32 %0, %1, %2;" : "=r"(hi) : "f"(y), "f"(x));
    float hx = __uint_as_float(hi << 16);
    float hy = __uint_as_float(hi & 0xFFFF0000u);
    asm("cvt.rn.bf16x2.f32 %0, %1, %2;" : "=r"(lo) : "f"(y - hy), "f"(x - hx));
    return hi;
}
__device__ __forceinline__ void mma_bf16(float4& c, const unsigned a[4], const unsigned b[2]) {
    asm volatile(
        "mma.sync.aligned.m16n8k16.row.col.f32.bf16.bf16.f32 "
        "{%0,%1,%2,%3}, {%4,%5,%6,%7}, {%8,%9}, {%0,%1,%2,%3};"
        : "+f"(c.x), "+f"(c.y), "+f"(c.z), "+f"(c.w)
        : "r"(a[0]), "r"(a[1]), "r"(a[2]), "r"(a[3]), "r"(b[0]), "r"(b[1]));
}

// ---------------- weight pre-split ----------------
__global__ void k_bsplit(const float* __restrict__ W0, const float* __restrict__ Ws) {
    int i = blockIdx.x * blockDim.x + threadIdx.x;
    if (i >= BS_TOT) return;
    const float* W;
    int p, n;
    if (i < BS_W0) {
        W = W0; p = i / HD; n = i % HD;
    } else {
        int j = i - BS_W0;
        int l = j / BS_WL;
        int r = j % BS_WL;
        W = Ws + (size_t)l * HD * HD;
        p = r / HD; n = r % HD;
    }
    float v0 = W[(size_t)(2 * p) * HD + n];
    float v1 = W[(size_t)(2 * p + 1) * HD + n];
    unsigned lo;
    unsigned hi = bf_split2(v0, v1, lo);
    g_Bsplit[i] = make_uint2(hi, lo);
}

// ---------------- CSR build ----------------
#define SCAN_B 256
__global__ void k_scan1() {
    __shared__ int sh[SCAN_B];
    int i = blockIdx.x * SCAN_B + threadIdx.x;
    int v = (i < NN) ? g_deg[i] : 0;
    sh[threadIdx.x] = v;
    __syncthreads();
    for (int s = SCAN_B / 2; s > 0; s >>= 1) {
        if (threadIdx.x < s) sh[threadIdx.x] += sh[threadIdx.x + s];
        __syncthreads();
    }
    if (threadIdx.x == 0) g_bsum[blockIdx.x] = sh[0];
}
__global__ void k_scan2p(int nblocks) {
    __shared__ int sh[256];
    int t = threadIdx.x;
    int v = (t < nblocks) ? g_bsum[t] : 0;
    sh[t] = v;
    __syncthreads();
    for (int s = 1; s < 256; s <<= 1) {
        int u = (t >= s) ? sh[t - s] : 0;
        __syncthreads();
        sh[t] += u;
        __syncthreads();
    }
    if (t < nblocks) g_boff[t] = sh[t] - v;
    if (t == 255) g_rowptr[NN] = sh[255];
}
__global__ void k_scan3() {
    __shared__ int sh[SCAN_B];
    int i = blockIdx.x * SCAN_B + threadIdx.x;
    int v = (i < NN) ? g_deg[i] : 0;
    sh[threadIdx.x] = v;
    __syncthreads();
    for (int s = 1; s < SCAN_B; s <<= 1) {
        int t = (threadIdx.x >= s) ? sh[threadIdx.x - s] : 0;
        __syncthreads();
        sh[threadIdx.x] += t;
        __syncthreads();
    }
    if (i < NN) {
        int excl = g_boff[blockIdx.x] + sh[threadIdx.x] - v;
        g_rowptr[i] = excl;
        g_pos[i] = excl;
        g_inv[i] = rsqrtf((float)(v + 1));
    }
}
__global__ void k_scatter(const int* __restrict__ src, const int* __restrict__ dst) {
    int e = blockIdx.x * blockDim.x + threadIdx.x;
    if (e >= NE) return;
    int d = dst[e];
    int slot = atomicAdd(&g_pos[d], 1);
    g_csrc[slot] = src[e];
}

// ---------------- small GEMM: g_R[l] = gh @ Ws[l] ----------------
__global__ __launch_bounds__(256)
void k_rgemm(const float* __restrict__ gh, const float* __restrict__ Ws) {
    __shared__ float Ag[128 * 36];
    __shared__ float Bg[32 * 132];
    const float* B = Ws + (size_t)blockIdx.y * HD * HD;
    const int colBase = blockIdx.x * 128;
    const int tid = threadIdx.x;
    const int tx = tid & 15, ty = tid >> 4;
    float acc[8][8];
#pragma unroll
    for (int i = 0; i < 8; i++)
#pragma unroll
        for (int j = 0; j < 8; j++) acc[i][j] = 0.f;

    const int ar = tid >> 1, ak = (tid & 1) * 16;
    const int br = tid >> 3, bc = (tid & 7) * 16;
    for (int kt = 0; kt < HD; kt += 32) {
#pragma unroll
        for (int q = 0; q < 4; q++) {
            float4 v = *(const float4*)(gh + (size_t)ar * HD + kt + ak + 4 * q);
            *(float4*)&Ag[ar * 36 + ak + 4 * q] = v;
            float4 w = *(const float4*)(B + (size_t)(kt + br) * HD + colBase + bc + 4 * q);
            *(float4*)&Bg[br * 132 + bc + 4 * q] = w;
        }
        __syncthreads();
#pragma unroll
        for (int kk = 0; kk < 32; kk++) {
            float a[8], b[8];
#pragma unroll
            for (int i = 0; i < 8; i++) a[i] = Ag[(ty * 8 + i) * 36 + kk];
            *(float4*)(b)     = *(const float4*)&Bg[kk * 132 + tx * 8];
            *(float4*)(b + 4) = *(const float4*)&Bg[kk * 132 + tx * 8 + 4];
#pragma unroll
            for (int i = 0; i < 8; i++)
#pragma unroll
                for (int j = 0; j < 8; j++) acc[i][j] = fmaf(a[i], b[j], acc[i][j]);
        }
        __syncthreads();
    }
    float* outp = g_R + (size_t)blockIdx.y * NG * HD;
#pragma unroll
    for (int i = 0; i < 8; i++)
#pragma unroll
        for (int j = 0; j < 2; j++)
            *(float4*)(outp + (size_t)(ty * 8 + i) * HD + colBase + tx * 8 + 4 * j) =
                make_float4(acc[i][4 * j], acc[i][4 * j + 1], acc[i][4 * j + 2], acc[i][4 * j + 3]);
}

// ---------------- main tensor GEMM: split-BF16 m16n8k16, 3-term ----------------
// LIDX < 0: A = g_z (KD=FD), out fp32 g_h += bias.
// LIDX >= 0: A = g_h, out fp16 g_t16 (+= R[batch]).
#define AS2_W 20
#define BS2_W 132
template<int KD, int LIDX>
__global__ __launch_bounds__(256, 2)
void k_gemm(const int* __restrict__ batch, const float* __restrict__ bias) {
    __shared__ uint2 As2[128 * AS2_W];
    __shared__ uint2 Bs2[16 * BS2_W];
    const int tid  = threadIdx.x;
    const int lane = tid & 31;
    const int warp = tid >> 5;
    const int wm = warp >> 1;
    const int wn = warp & 1;
    const int rowBase = blockIdx.x * 128;
    const int colBase = blockIdx.y * 128;

    const int arow = tid >> 1;
    const int akh  = tid & 1;
    const int bk   = tid >> 4;
    const int bc8  = (tid & 15) * 8;

    const int aRowG = rowBase + arow;
    const bool rowOK = (aRowG < NN);
    const float* aPtr = (LIDX < 0 ? (const float*)g_z : (const float*)g_h) + (size_t)aRowG * KD;
    const uint2* B2 = g_Bsplit + (LIDX < 0 ? 0 : BS_W0 + (size_t)LIDX * BS_WL);

    float4 acc[2][8];
#pragma unroll
    for (int i = 0; i < 2; i++)
#pragma unroll
        for (int j = 0; j < 8; j++) acc[i][j] = make_float4(0.f, 0.f, 0.f, 0.f);

    for (int kt = 0; kt < KD; kt += 32) {
        {
            float av[16];
#pragma unroll
            for (int q = 0; q < 4; q++) {
                float4 v = make_float4(0.f, 0.f, 0.f, 0.f);
                if (rowOK) v = *(const float4*)(aPtr + kt + akh * 16 + 4 * q);
                av[4 * q] = v.x; av[4 * q + 1] = v.y; av[4 * q + 2] = v.z; av[4 * q + 3] = v.w;
            }
#pragma unroll
            for (int p = 0; p < 4; p++) {
                unsigned lo0, lo1;
                unsigned hi0 = bf_split2(av[4 * p],     av[4 * p + 1], lo0);
                unsigned hi1 = bf_split2(av[4 * p + 2], av[4 * p + 3], lo1);
                *(uint4*)&As2[arow * AS2_W + akh * 8 + 2 * p] = make_uint4(hi0, lo0, hi1, lo1);
            }
        }
        {
            const uint2* bg = B2 + (size_t)(kt / 2 + bk) * HD + colBase + bc8;
            uint2* bs = &Bs2[bk * BS2_W + bc8];
#pragma unroll
            for (int i = 0; i < 4; i++)
                *(uint4*)(bs + i * 2) = *(const uint4*)(bg + i * 2);
        }
        __syncthreads();

#pragma unroll
        for (int s = 0; s < 2; s++) {
            const int kp = s * 8 + (lane & 3);
            unsigned ah[2][4], al[2][4];
#pragma unroll
            for (int i = 0; i < 2; i++) {
                int r = wm * 32 + i * 16 + (lane >> 2);
                uint2 p0 = As2[r * AS2_W + kp];
                uint2 p1 = As2[(r + 8) * AS2_W + kp];
                uint2 p2 = As2[r * AS2_W + kp + 4];
                uint2 p3 = As2[(r + 8) * AS2_W + kp + 4];
                ah[i][0] = p0.x; al[i][0] = p0.y;
                ah[i][1] = p1.x; al[i][1] = p1.y;
                ah[i][2] = p2.x; al[i][2] = p2.y;
                ah[i][3] = p3.x; al[i][3] = p3.y;
            }
#pragma unroll
            for (int h = 0; h < 2; h++) {
                unsigned bh[4][2], bl[4][2];
#pragma unroll
                for (int j = 0; j < 4; j++) {
                    int col = wn * 64 + h * 32 + j * 8 + (lane >> 2);
                    uint2 q0 = Bs2[kp * BS2_W + col];
                    uint2 q1 = Bs2[(kp + 4) * BS2_W + col];
                    bh[j][0] = q0.x; bl[j][0] = q0.y;
                    bh[j][1] = q1.x; bl[j][1] = q1.y;
                }
#pragma unroll
                for (int i = 0; i < 2; i++)
#pragma unroll
                    for (int j = 0; j < 4; j++) {
                        float4& c4 = acc[i][h * 4 + j];
                        mma_bf16(c4, ah[i], bh[j]);
                        mma_bf16(c4, ah[i], bl[j]);
                        mma_bf16(c4, al[i], bh[j]);
                    }
            }
        }
        __syncthreads();
    }

#pragma unroll
    for (int i = 0; i < 2; i++) {
        int r0 = rowBase + wm * 32 + i * 16 + (lane >> 2);
        const float* Ra = nullptr;
        const float* Rb = nullptr;
        if (LIDX >= 0) {
            if (r0 < NN)     Ra = g_R + (size_t)LIDX * NG * HD + (size_t)batch[r0] * HD;
            if (r0 + 8 < NN) Rb = g_R + (size_t)LIDX * NG * HD + (size_t)batch[r0 + 8] * HD;
        }
#pragma unroll
        for (int j = 0; j < 8; j++) {
            int c = colBase + wn * 64 + j * 8 + 2 * (lane & 3);
            float4 v = acc[i][j];
            if (LIDX < 0) {
                float2 bc2 = *(const float2*)(bias + c);
                if (r0 < NN) {
                    *(float2*)(g_h + (size_t)r0 * HD + c) = make_float2(v.x + bc2.x, v.y + bc2.y);
                }
                if (r0 + 8 < NN) {
                    *(float2*)(g_h + (size_t)(r0 + 8) * HD + c) = make_float2(v.z + bc2.x, v.w + bc2.y);
                }
            } else {
                if (r0 < NN) {
                    float2 r = *(const float2*)(Ra + c);
                    *(__half2*)((__half*)g_t16 + (size_t)r0 * HD + c) =
                        __floats2half2_rn(v.x + r.x, v.y + r.y);
                }
                if (r0 + 8 < NN) {
                    float2 r = *(const float2*)(Rb + c);
                    *(__half2*)((__half*)g_t16 + (size_t)(r0 + 8) * HD + c) =
                        __floats2half2_rn(v.z + r.x, v.w + r.y);
                }
            }
        }
    }
}

// ---------------- propagation ----------------
__device__ __forceinline__ void acc4(float4& acc, const float4& u, float wt) {
    acc.x = fmaf(u.x, wt, acc.x);
    acc.y = fmaf(u.y, wt, acc.y);
    acc.z = fmaf(u.z, wt, acc.z);
    acc.w = fmaf(u.w, wt, acc.w);
}
__device__ __forceinline__ float4 ld_h16(const __half* p) {
    uint2 u = *(const uint2*)p;
    __half2 a = *(__half2*)&u.x;
    __half2 b = *(__half2*)&u.y;
    float2 fa = __half22float2(a);
    float2 fb = __half22float2(b);
    return make_float4(fa.x, fa.y, fb.x, fb.y);
}

// z = P x  (N x 128, fp32). One warp per node.
__global__ __launch_bounds__(256)
void k_prop_x(const float* __restrict__ x) {
    int node = blockIdx.x * 8 + (threadIdx.x >> 5);
    int lane = threadIdx.x & 31;
    if (node >= NN) return;
    int off = lane * 4;
    float invd = g_inv[node];
    float sq = invd * invd;
    float4 h0 = *(const float4*)(x + (size_t)node * FD + off);
    float4 acc = make_float4(h0.x * sq, h0.y * sq, h0.z * sq, h0.w * sq);
    int e   = g_rowptr[node];
    int end = g_rowptr[node + 1];
    for (; e + 8 <= end; e += 8) {
        int s[8];
        float wt[8];
        float4 u[8];
#pragma unroll
        for (int q = 0; q < 8; q++) s[q] = g_csrc[e + q];
#pragma unroll
        for (int q = 0; q < 8; q++) u[q] = *(const float4*)(x + (size_t)s[q] * FD + off);
#pragma unroll
        for (int q = 0; q < 8; q++) wt[q] = g_inv[s[q]] * invd;
#pragma unroll
        for (int q = 0; q < 8; q++) acc4(acc, u[q], wt[q]);
    }
    for (; e < end; e++) {
        int s0 = g_csrc[e];
        float w0 = g_inv[s0] * invd;
        float4 u0 = *(const float4*)(x + (size_t)s0 * FD + off);
        acc4(acc, u0, w0);
    }
    *(float4*)(g_z + (size_t)node * FD + off) = acc;
}

// h = relu(P t + bias), t in fp16 g_t16; POOL=false: write g_h; POOL=true: reduce g_gmsum.
template<bool POOL>
__global__ __launch_bounds__(256)
void k_prop(const float* __restrict__ bias, const int* __restrict__ batch) {
    int node = blockIdx.x * 4 + (threadIdx.x >> 6);
    int half = (threadIdx.x >> 5) & 1;
    int lane = threadIdx.x & 31;
    if (node >= NN) return;
    int off = half * 128 + lane * 4;
    float invd = g_inv[node];
    float sq = invd * invd;
    float4 h0 = ld_h16((const __half*)g_t16 + (size_t)node * HD + off);
    float4 b0 = *(const float4*)(bias + off);
    float4 acc = make_float4(fmaf(h0.x, sq, b0.x), fmaf(h0.y, sq, b0.y),
                             fmaf(h0.z, sq, b0.z), fmaf(h0.w, sq, b0.w));
    int e   = g_rowptr[node];
    int end = g_rowptr[node + 1];
    for (; e + 8 <= end; e += 8) {
        int s[8];
        float wt[8];
        float4 u[8];
#pragma unroll
        for (int q = 0; q < 8; q++) s[q] = g_csrc[e + q];
#pragma unroll
        for (int q = 0; q < 8; q++) u[q] = ld_h16((const __half*)g_t16 + (size_t)s[q] * HD + off);
#pragma unroll
        for (int q = 0; q < 8; q++) wt[q] = g_inv[s[q]] * invd;
#pragma unroll
        for (int q = 0; q < 8; q++) acc4(acc, u[q], wt[q]);
    }
    for (; e + 2 <= end; e += 2) {
        int s0 = g_csrc[e], s1 = g_csrc[e + 1];
        float4 u0 = ld_h16((const __half*)g_t16 + (size_t)s0 * HD + off);
        float4 u1 = ld_h16((const __half*)g_t16 + (size_t)s1 * HD + off);
        float w0 = g_inv[s0] * invd, w1 = g_inv[s1] * invd;
        acc4(acc, u0, w0);
        acc4(acc, u1, w1);
    }
    if (e < end) {
        int s0 = g_csrc[e];
        float w0 = g_inv[s0] * invd;
        float4 u0 = ld_h16((const __half*)g_t16 + (size_t)s0 * HD + off);
        acc4(acc, u0, w0);
    }
    acc.x = fmaxf(acc.x, 0.f); acc.y = fmaxf(acc.y, 0.f);
    acc.z = fmaxf(acc.z, 0.f); acc.w = fmaxf(acc.w, 0.f);
    if (POOL) {
        float* gs = g_gmsum + (size_t)batch[node] * HD + off;
        asm volatile("red.global.add.v4.f32 [%0], {%1,%2,%3,%4};"
                     :: "l"(gs), "f"(acc.x), "f"(acc.y), "f"(acc.z), "f"(acc.w) : "memory");
    } else {
        *(float4*)(g_h + (size_t)node * HD + off) = acc;
    }
}

// ---------------- fused gm + head ----------------
__global__ __launch_bounds__(256)
void k_head(const float* __restrict__ gh, const float* __restrict__ Wlin,
            const float* __restrict__ blin, float* __restrict__ out) {
    __shared__ float gm[HD];
    int g = blockIdx.x;
    int t = threadIdx.x;
    float cnt = (float)max(g_cnt[g], 1);
    float v = g_gmsum[g * HD + t] / cnt + gh[g * HD + t];
    gm[t] = v;
    out[NG * NC + g * HD + t] = v;
    __syncthreads();
    if (t < NC) {
        float s = blin[t];
#pragma unroll 8
        for (int k = 0; k < HD; k++) s = fmaf(gm[k], Wlin[k * NC + t], s);
        out[g * NC + t] = s;
    }
}

// ---------------- launch ----------------
extern "C" void kernel_launch(void* const* d_in, const int* in_sizes, int n_in,
                              void* d_out, int out_size) {
    const float* x     = (const float*)d_in[0];
    const int*   ei    = (const int*)d_in[1];
    const int*   src   = ei;
    const int*   dst   = ei + NE;
    const int*   batch = (const int*)d_in[2];
    const float* gh    = (const float*)d_in[3];
    const float* W0    = (const float*)d_in[4];
    const float* b0    = (const float*)d_in[5];
    const float* Ws    = (const float*)d_in[6];
    const float* bs    = (const float*)d_in[7];
    const float* Wlin  = (const float*)d_in[8];
    const float* blin  = (const float*)d_in[9];
    float* out = (float*)d_out;

    dim3 ggrid((NN + 127) / 128, HD / 128);
    const int propBlocks  = (NN + 3) / 4;
    const int propxBlocks = (NN + 7) / 8;
    const int nsb = (NN + SCAN_B - 1) / SCAN_B;

    k_init<<<(NN + 255) / 256, 256>>>();
    k_count<<<(NE + 255) / 256, 256>>>(dst, batch);
    k_scan1<<<nsb, SCAN_B>>>();
    k_bsplit<<<(BS_TOT + 255) / 256, 256>>>(W0, Ws);
    k_scan2p<<<1, 256>>>(nsb);
    k_scan3<<<nsb, SCAN_B>>>();
    k_scatter<<<(NE + 255) / 256, 256>>>(src, dst);
    k_rgemm<<<dim3(2, NL), 256>>>(gh, Ws);

    // layer 0: z = P x (narrow) ; h0 = z @ W0 + b0  (fp32 path)
    k_prop_x<<<propxBlocks, 256>>>(x);
    k_gemm<FD, -1><<<ggrid, 256>>>(nullptr, b0);

    // hidden layers: t16 = h @ Ws[l] + R_l[batch] (fp16) ; h = relu(P t16 + bs[l])
    k_gemm<HD, 0><<<ggrid, 256>>>(batch, nullptr);
    k_prop<false><<<propBlocks, 256>>>(bs + 0 * HD, nullptr);
    k_gemm<HD, 1><<<ggrid, 256>>>(batch, nullptr);
    k_prop<false><<<propBlocks, 256>>>(bs + 1 * HD, nullptr);
    k_gemm<HD, 2><<<ggrid, 256>>>(batch, nullptr);
    k_prop<true><<<propBlocks, 256>>>(bs + 2 * HD, batch);   // pool fused

    k_head<<<NG, 256>>>(gh, Wlin, blin, out);
}